// round 4
// baseline (speedup 1.0000x reference)
#include <cuda_runtime.h>
#include <cstdint>
#include <cstddef>

// ---------------------------------------------------------------------------
// Problem constants
// ---------------------------------------------------------------------------
#define BATCH   256
#define SEQ     512
#define NIN     256
#define HID     256
#define G3      768          // 3*HID
#define LAYERS  2
#define ROWS    (BATCH*SEQ)  // 131072
#define RANKSUM 96           // 64 + 32

// ---------------------------------------------------------------------------
// Static device scratch (no cudaMalloc allowed)
// ---------------------------------------------------------------------------
__device__ float g_t_buf[(size_t)ROWS * RANKSUM];   //  50 MB  stage-1 of wx
__device__ float g_wx_buf[(size_t)ROWS * G3];       // 403 MB  wx (all t)
__device__ float g_x1[(size_t)ROWS * HID];          // 134 MB  layer-0 output
__device__ float g_P [LAYERS * NIN * RANKSUM];      // [Wd|Wo]
__device__ float g_Q [LAYERS * RANKSUM * G3];       // [Wdg;Wog]
__device__ float g_Pu[LAYERS * HID * RANKSUM];      // [Ud|Uo]
__device__ float g_Qu[LAYERS * RANKSUM * G3];       // [Udg;Uog]
__device__ float g_Ueff[LAYERS * HID * G3];         // dense recurrent weight
__device__ float g_h [2 * 16 * HID * 16];           // h double buffer [buf][grp][k][b]

// ---------------------------------------------------------------------------
// Pack kernel: concatenate low-rank factors
// ---------------------------------------------------------------------------
__global__ void pack_kernel(const float* __restrict__ Wd, const float* __restrict__ Wdg,
                            const float* __restrict__ Wo, const float* __restrict__ Wog,
                            const float* __restrict__ Ud, const float* __restrict__ Udg,
                            const float* __restrict__ Uo, const float* __restrict__ Uog)
{
    int idx = blockIdx.x * 256 + threadIdx.x;
    const int QN = LAYERS * RANKSUM * G3;   // 147456
    const int PN = LAYERS * NIN * RANKSUM;  // 49152
    if (idx < QN) {
        int l = idx / (RANKSUM * G3);
        int rem = idx - l * (RANKSUM * G3);
        int r = rem / G3, n = rem - r * G3;
        g_Q[idx]  = (r < 64) ? Wdg[(l*64 + r) * G3 + n] : Wog[(l*32 + (r-64)) * G3 + n];
        g_Qu[idx] = (r < 64) ? Udg[(l*64 + r) * G3 + n] : Uog[(l*32 + (r-64)) * G3 + n];
    }
    if (idx < PN) {
        int l = idx / (NIN * RANKSUM);
        int rem = idx - l * (NIN * RANKSUM);
        int k = rem / RANKSUM, j = rem - k * RANKSUM;
        g_P[idx]  = (j < 64) ? Wd[(l*NIN + k) * 64 + j] : Wo[(l*NIN + k) * 32 + (j-64)];
        g_Pu[idx] = (j < 64) ? Ud[(l*NIN + k) * 64 + j] : Uo[(l*NIN + k) * 32 + (j-64)];
    }
}

// ---------------------------------------------------------------------------
// Generic tiled fp32 GEMM: C[M,N] = A[M,K] @ B[K,N] (+ bias)
// BM=64, BN=64, BK=16, 256 threads, 4x4 microtile. M%64==0, K%16==0, N%4==0.
// ---------------------------------------------------------------------------
__global__ void __launch_bounds__(256)
gemm_tiled(const float* __restrict__ A, const float* __restrict__ B,
           const float* __restrict__ bias, float* __restrict__ C,
           int M, int N, int K)
{
    __shared__ float As[16][64];
    __shared__ float Bs[16][68];

    const int tid = threadIdx.x;
    const int tm = tid >> 4, tn = tid & 15;
    const size_t bm = (size_t)blockIdx.x * 64;
    const int bn = blockIdx.y * 64;

    const int ar = tid >> 2, ak = (tid & 3) << 2;
    const int brow = tid >> 4, bcol = (tid & 15) << 2;

    float acc[4][4];
#pragma unroll
    for (int i = 0; i < 4; ++i)
#pragma unroll
        for (int j = 0; j < 4; ++j) acc[i][j] = 0.f;

    for (int k0 = 0; k0 < K; k0 += 16) {
        float4 av = *(const float4*)(A + (bm + ar) * (size_t)K + k0 + ak);
        As[ak + 0][ar] = av.x; As[ak + 1][ar] = av.y;
        As[ak + 2][ar] = av.z; As[ak + 3][ar] = av.w;

        float4 bv = make_float4(0.f, 0.f, 0.f, 0.f);
        if (bn + bcol < N)
            bv = *(const float4*)(B + (size_t)(k0 + brow) * N + bn + bcol);
        *(float4*)&Bs[brow][bcol] = bv;
        __syncthreads();

#pragma unroll
        for (int k = 0; k < 16; ++k) {
            float4 a = *(const float4*)&As[k][tm << 2];
            float4 b = *(const float4*)&Bs[k][tn << 2];
            acc[0][0] = fmaf(a.x, b.x, acc[0][0]); acc[0][1] = fmaf(a.x, b.y, acc[0][1]);
            acc[0][2] = fmaf(a.x, b.z, acc[0][2]); acc[0][3] = fmaf(a.x, b.w, acc[0][3]);
            acc[1][0] = fmaf(a.y, b.x, acc[1][0]); acc[1][1] = fmaf(a.y, b.y, acc[1][1]);
            acc[1][2] = fmaf(a.y, b.z, acc[1][2]); acc[1][3] = fmaf(a.y, b.w, acc[1][3]);
            acc[2][0] = fmaf(a.z, b.x, acc[2][0]); acc[2][1] = fmaf(a.z, b.y, acc[2][1]);
            acc[2][2] = fmaf(a.z, b.z, acc[2][2]); acc[2][3] = fmaf(a.z, b.w, acc[2][3]);
            acc[3][0] = fmaf(a.w, b.x, acc[3][0]); acc[3][1] = fmaf(a.w, b.y, acc[3][1]);
            acc[3][2] = fmaf(a.w, b.z, acc[3][2]); acc[3][3] = fmaf(a.w, b.w, acc[3][3]);
        }
        __syncthreads();
    }

#pragma unroll
    for (int i = 0; i < 4; ++i) {
        size_t row = bm + (tm << 2) + i;
#pragma unroll
        for (int j = 0; j < 4; ++j) {
            int colj = bn + (tn << 2) + j;
            if (colj < N) {
                float v = acc[i][j];
                if (bias) v += bias[colj];
                C[row * (size_t)N + colj] = v;
            }
        }
    }
}

// ---------------------------------------------------------------------------
// Persistent recurrent kernel, v3 (latency-optimized scalar FFMA).
//
// Cluster of 8 CTAs = one batch group of 16 rows. CTA c owns h-cols
// [32c,32c+32) and matching z/r/c cols of Ueff (96 KB stationary SMEM,
// layout [k][gate][32]). h exchanged via L2-resident global double buffer.
//
// 512 threads = 16 warps: kq = w>>2 (k-quarter, 64 k), ws = w&3 (row quad,
// rows 4ws..4ws+3). NOTE ws == SMSP id, so every SMSP hosts 4 warps during
// the k-loop (FFMA port saturated) and exactly one epilogue (kq==0) warp.
// Thread = 4 rows x 1 col x 3 gates = 12 FFMA/k. kq>0 partials reduced
// through smem once per step. Cluster barrier split: publish -> arrive ->
// out_x stores -> wait -> h reload.
// ---------------------------------------------------------------------------
#define RED_FLOATS (3 * 4 * 32 * 12)                       // 4608
#define RNN_SMEM   ((HID*96 + HID*16 + RED_FLOATS) * 4)    // 98304+16384+18432

__device__ __forceinline__ float sigmoidf_(float x)
{
    return __fdividef(1.f, 1.f + __expf(-x));
}
__device__ __forceinline__ float tanhf_(float x)
{
    return __fdividef(2.f, 1.f + __expf(-2.f * x)) - 1.f;
}

__global__ void __cluster_dims__(8, 1, 1) __launch_bounds__(512, 1)
rnn_kernel(const float* __restrict__ Ueff,   // [256,768] this layer
           const float* __restrict__ wx,     // [B*T,768]
           float* __restrict__ out_x,        // [B*T,256]
           float* __restrict__ hT_out,       // out + OUT0 + l*256, idx b*512+col
           float* __restrict__ hbuf)         // g_h
{
    extern __shared__ float smem[];
    float* sU  = smem;            // [256 k][3 gates][32 cols]
    float* sh_ = smem + HID * 96; // [256 k][16 rows]
    float* red = sh_ + HID * 16;  // [3][4 ws][32 lane][12]

    const int c  = blockIdx.x & 7;      // column group (== cluster rank)
    const int g  = blockIdx.x >> 3;     // batch group
    const int tid = threadIdx.x;
    const int w = tid >> 5, lane = tid & 31;
    const int kq = w >> 2;              // k-quarter 0..3
    const int ws = w & 3;               // row quad 0..3 (== SMSP)
    const int b0 = g << 4;

    // Stationary Ueff slice, interleaved [k][gate][32 cols]
    for (int idx = tid; idx < HID * 96; idx += 512) {
        int k = idx / 96, r = idx - k * 96;
        sU[idx] = Ueff[k * G3 + ((r >> 5) << 8) + (c << 5) + (r & 31)];
    }
    // h0 = 0
    for (int i = tid; i < 1024; i += 512)
        ((float4*)sh_)[i] = make_float4(0.f, 0.f, 0.f, 0.f);
    __syncthreads();

    const int col = (c << 5) + lane;    // owned global h column
    const int r0  = ws << 2;            // first owned row (of 16)
    const int kbase = kq << 6;

    for (int t = 0; t < SEQ; ++t) {
        // ---- prefetch wx for this step (only epilogue warps) ----
        float wz[4], wr[4], wc[4];
        if (kq == 0) {
#pragma unroll
            for (int i = 0; i < 4; ++i) {
                const float* p = wx + ((size_t)(b0 + r0 + i) * SEQ + t) * G3 + col;
                wz[i] = p[0]; wr[i] = p[256]; wc[i] = p[512];
            }
        }

        // ---- partial uh over this warp's k-quarter ----
        float az[4] = {0.f, 0.f, 0.f, 0.f};
        float ar[4] = {0.f, 0.f, 0.f, 0.f};
        float ac[4] = {0.f, 0.f, 0.f, 0.f};
        {
            const float* hP = sh_ + (kbase << 4) + r0;
            const float* uP = sU + kbase * 96 + lane;
#pragma unroll 8
            for (int kk = 0; kk < 64; ++kk) {
                const float4 hq = *(const float4*)hP;
                const float uz = uP[0], ur = uP[32], uc = uP[64];
                az[0] = fmaf(hq.x, uz, az[0]); ar[0] = fmaf(hq.x, ur, ar[0]); ac[0] = fmaf(hq.x, uc, ac[0]);
                az[1] = fmaf(hq.y, uz, az[1]); ar[1] = fmaf(hq.y, ur, ar[1]); ac[1] = fmaf(hq.y, uc, ac[1]);
                az[2] = fmaf(hq.z, uz, az[2]); ar[2] = fmaf(hq.z, ur, ar[2]); ac[2] = fmaf(hq.z, uc, ac[2]);
                az[3] = fmaf(hq.w, uz, az[3]); ar[3] = fmaf(hq.w, ur, ar[3]); ac[3] = fmaf(hq.w, uc, ac[3]);
                hP += 16; uP += 96;
            }
        }

        // ---- k-split reduction through smem ----
        if (kq != 0) {
            float* s = red + (((kq - 1) * 4 + ws) * 32 + lane) * 12;
            *(float4*)(s + 0) = make_float4(az[0], az[1], az[2], az[3]);
            *(float4*)(s + 4) = make_float4(ar[0], ar[1], ar[2], ar[3]);
            *(float4*)(s + 8) = make_float4(ac[0], ac[1], ac[2], ac[3]);
        }
        __syncthreads();

        float hn[4];
        if (kq == 0) {
#pragma unroll
            for (int q = 0; q < 3; ++q) {
                const float* s = red + ((q * 4 + ws) * 32 + lane) * 12;
                const float4 vz = *(const float4*)(s + 0);
                const float4 vr = *(const float4*)(s + 4);
                const float4 vc = *(const float4*)(s + 8);
                az[0] += vz.x; az[1] += vz.y; az[2] += vz.z; az[3] += vz.w;
                ar[0] += vr.x; ar[1] += vr.y; ar[2] += vr.z; ar[3] += vr.w;
                ac[0] += vc.x; ac[1] += vc.y; ac[2] += vc.z; ac[3] += vc.w;
            }

            // ---- gates + h update (4 rows x 1 col per lane) ----
            const float4 hp4 = *(const float4*)(sh_ + (col << 4) + r0);
            const float hp[4] = {hp4.x, hp4.y, hp4.z, hp4.w};
#pragma unroll
            for (int i = 0; i < 4; ++i) {
                const float z = sigmoidf_(wz[i] + az[i]);
                const float r = sigmoidf_(wr[i] + ar[i]);
                const float cc = tanhf_(wc[i] + r * ac[i]);
                hn[i] = z * hp[i] + (1.f - z) * cc;
            }

            // publish h_{t+1} slice to the group double buffer
            const int nb = (t + 1) & 1;
            float* hg = hbuf + (((size_t)nb * 16 + g) * HID + col) * 16 + r0;
            *(float4*)hg = make_float4(hn[0], hn[1], hn[2], hn[3]);

            if (t == SEQ - 1) {
#pragma unroll
                for (int i = 0; i < 4; ++i)
                    hT_out[(size_t)(b0 + r0 + i) * 512 + col] = hn[i];
            }
        }

        // cluster barrier (arrive releases the hbuf stores)
        asm volatile("barrier.cluster.arrive.aligned;" ::: "memory");

        // out_x stores are not consumed by peers -> issue between arrive/wait
        if (kq == 0) {
#pragma unroll
            for (int i = 0; i < 4; ++i)
                out_x[((size_t)(b0 + r0 + i) * SEQ + t) * HID + col] = hn[i];
        }

        asm volatile("barrier.cluster.wait.aligned;" ::: "memory");

        // reload full h_{t+1} for this group into SMEM (2 float4 per thread)
        const int nb = (t + 1) & 1;
        const float4* src = (const float4*)(hbuf + (size_t)(nb * 16 + g) * HID * 16);
        ((float4*)sh_)[tid]       = src[tid];
        ((float4*)sh_)[tid + 512] = src[tid + 512];
        __syncthreads();
    }
}

// ---------------------------------------------------------------------------
// Launch
// ---------------------------------------------------------------------------
extern "C" void kernel_launch(void* const* d_in, const int* in_sizes, int n_in,
                              void* d_out, int out_size)
{
    const float* x   = (const float*)d_in[0];
    const float* Wd  = (const float*)d_in[1];
    const float* Wdg = (const float*)d_in[2];
    const float* Wo  = (const float*)d_in[3];
    const float* Wog = (const float*)d_in[4];
    const float* Ud  = (const float*)d_in[5];
    const float* Udg = (const float*)d_in[6];
    const float* Uo  = (const float*)d_in[7];
    const float* Uog = (const float*)d_in[8];
    const float* bb  = (const float*)d_in[9];
    float* out = (float*)d_out;

    float *pT, *pWX, *pX1, *pP, *pQ, *pPu, *pQu, *pUeff, *pH;
    cudaGetSymbolAddress((void**)&pT,   g_t_buf);
    cudaGetSymbolAddress((void**)&pWX,  g_wx_buf);
    cudaGetSymbolAddress((void**)&pX1,  g_x1);
    cudaGetSymbolAddress((void**)&pP,   g_P);
    cudaGetSymbolAddress((void**)&pQ,   g_Q);
    cudaGetSymbolAddress((void**)&pPu,  g_Pu);
    cudaGetSymbolAddress((void**)&pQu,  g_Qu);
    cudaGetSymbolAddress((void**)&pUeff, g_Ueff);
    cudaGetSymbolAddress((void**)&pH,   g_h);

    cudaFuncSetAttribute(rnn_kernel, cudaFuncAttributeMaxDynamicSharedMemorySize, RNN_SMEM);

    // 1. pack low-rank factors
    pack_kernel<<<(LAYERS * RANKSUM * G3 + 255) / 256, 256>>>(Wd, Wdg, Wo, Wog,
                                                              Ud, Udg, Uo, Uog);
    // 2. dense recurrent weights: Ueff[l] = Pu[l] @ Qu[l]  (256x768, K=96)
    for (int l = 0; l < LAYERS; ++l)
        gemm_tiled<<<dim3(HID / 64, G3 / 64), 256>>>(
            pPu + (size_t)l * HID * RANKSUM, pQu + (size_t)l * RANKSUM * G3,
            nullptr, pUeff + (size_t)l * HID * G3, HID, G3, RANKSUM);

    const size_t OUT0 = (size_t)ROWS * HID;   // 33,554,432

    for (int l = 0; l < LAYERS; ++l) {
        const float* xin = (l == 0) ? x : pX1;
        // 3. stage-1: T = x @ [Wd|Wo]   (131072 x 96, K=256)
        gemm_tiled<<<dim3(ROWS / 64, 2), 256>>>(
            xin, pP + (size_t)l * NIN * RANKSUM, nullptr, pT, ROWS, RANKSUM, NIN);
        // 4. stage-2: wx = T @ [Wdg;Wog] + b   (131072 x 768, K=96)
        gemm_tiled<<<dim3(ROWS / 64, G3 / 64), 256>>>(
            pT, pQ + (size_t)l * RANKSUM * G3, bb + l * G3, pWX, ROWS, G3, RANKSUM);
        // 5. sequential scan (persistent cluster kernel)
        float* ox = (l == LAYERS - 1) ? out : pX1;
        rnn_kernel<<<128, 512, RNN_SMEM>>>(
            pUeff + (size_t)l * HID * G3, pWX, ox, out + OUT0 + l * HID, pH);
    }
}

// round 6
// speedup vs baseline: 1.3341x; 1.3341x over previous
#include <cuda_runtime.h>
#include <cuda_bf16.h>
#include <cstdint>
#include <cstddef>

// ---------------------------------------------------------------------------
// Problem constants
// ---------------------------------------------------------------------------
#define BATCH   256
#define SEQ     512
#define NIN     256
#define HID     256
#define G3      768
#define LAYERS  2
#define ROWS    (BATCH*SEQ)
#define RANKSUM 96

// ---------------------------------------------------------------------------
// Static device scratch (no cudaMalloc allowed)
// ---------------------------------------------------------------------------
__device__ float g_t_buf[(size_t)ROWS * RANKSUM];
__device__ float g_wx_buf[(size_t)ROWS * G3];
__device__ float g_x1[(size_t)ROWS * HID];
__device__ float g_P [LAYERS * NIN * RANKSUM];
__device__ float g_Q [LAYERS * RANKSUM * G3];
__device__ float g_Pu[LAYERS * HID * RANKSUM];
__device__ float g_Qu[LAYERS * RANKSUM * G3];
__device__ float g_Ueff[LAYERS * HID * G3];

// U as bf16 hi/lo in B-operand layout: per (layer, cta): [96 n][264 k-padded]
#define BPAD  264                         // 528 bytes per row (bank step 4)
#define BTILE (96 * BPAD)                 // elems per (l, c) per precision
__device__ __nv_bfloat16 g_Uhi[(size_t)LAYERS * 8 * BTILE];
__device__ __nv_bfloat16 g_Ulo[(size_t)LAYERS * 8 * BTILE];

// h exchange: A-tile images [buf 2][group 16][hi 12288B | lo 12288B]
__device__ __nv_bfloat16 g_hx[2 * 16 * 2 * 6144];

// ---------------------------------------------------------------------------
// PTX helpers (baseline-target-safe: ldmatrix + mma.sync only)
// ---------------------------------------------------------------------------
__device__ __forceinline__ uint32_t smem_u32(const void* p)
{
    uint32_t a;
    asm("{ .reg .u64 t; cvta.to.shared.u64 t, %1; cvt.u32.u64 %0, t; }"
        : "=r"(a) : "l"(p));
    return a;
}

#define LDSM4(R, addr) \
    asm volatile("ldmatrix.sync.aligned.m8n8.x4.shared.b16 {%0,%1,%2,%3}, [%4];" \
        : "=r"((R)[0]), "=r"((R)[1]), "=r"((R)[2]), "=r"((R)[3]) : "r"(addr))
#define LDSM2(R, addr) \
    asm volatile("ldmatrix.sync.aligned.m8n8.x2.shared.b16 {%0,%1}, [%2];" \
        : "=r"((R)[0]), "=r"((R)[1]) : "r"(addr))
#define MMA16816(D, A, B) \
    asm volatile("mma.sync.aligned.m16n8k16.row.col.f32.bf16.bf16.f32 " \
        "{%0,%1,%2,%3}, {%4,%5,%6,%7}, {%8,%9}, {%0,%1,%2,%3};" \
        : "+f"((D)[0]), "+f"((D)[1]), "+f"((D)[2]), "+f"((D)[3]) \
        : "r"((A)[0]), "r"((A)[1]), "r"((A)[2]), "r"((A)[3]), \
          "r"((B)[0]), "r"((B)[1]))

// ---------------------------------------------------------------------------
// Pack kernel: concatenate low-rank factors
// ---------------------------------------------------------------------------
__global__ void pack_kernel(const float* __restrict__ Wd, const float* __restrict__ Wdg,
                            const float* __restrict__ Wo, const float* __restrict__ Wog,
                            const float* __restrict__ Ud, const float* __restrict__ Udg,
                            const float* __restrict__ Uo, const float* __restrict__ Uog)
{
    int idx = blockIdx.x * 256 + threadIdx.x;
    const int QN = LAYERS * RANKSUM * G3;
    const int PN = LAYERS * NIN * RANKSUM;
    if (idx < QN) {
        int l = idx / (RANKSUM * G3);
        int rem = idx - l * (RANKSUM * G3);
        int r = rem / G3, n = rem - r * G3;
        g_Q[idx]  = (r < 64) ? Wdg[(l*64 + r) * G3 + n] : Wog[(l*32 + (r-64)) * G3 + n];
        g_Qu[idx] = (r < 64) ? Udg[(l*64 + r) * G3 + n] : Uog[(l*32 + (r-64)) * G3 + n];
    }
    if (idx < PN) {
        int l = idx / (NIN * RANKSUM);
        int rem = idx - l * (NIN * RANKSUM);
        int k = rem / RANKSUM, j = rem - k * RANKSUM;
        g_P[idx]  = (j < 64) ? Wd[(l*NIN + k) * 64 + j] : Wo[(l*NIN + k) * 32 + (j-64)];
        g_Pu[idx] = (j < 64) ? Ud[(l*NIN + k) * 64 + j] : Uo[(l*NIN + k) * 32 + (j-64)];
    }
}

// ---------------------------------------------------------------------------
// Split Ueff into bf16 hi/lo in B-operand layout.
// n (0..95) = gate-major col of this CTA: gate = n>>5, j = n&31,
// gatecol = gate*256 + c*32 + j;  element = Ueff[l][k][gatecol].
// ---------------------------------------------------------------------------
__global__ void split_u()
{
    int idx = blockIdx.x * 256 + threadIdx.x;          // l*8*96*256 total
    if (idx >= LAYERS * 8 * 96 * 256) return;
    int k = idx & 255;
    int n = (idx >> 8) % 96;
    int c = (idx >> 8) / 96 % 8;
    int l = idx / (8 * 96 * 256);
    int gatecol = ((n >> 5) << 8) + (c << 5) + (n & 31);
    float v = g_Ueff[(size_t)l * HID * G3 + (size_t)k * G3 + gatecol];
    __nv_bfloat16 hi = __float2bfloat16(v);
    __nv_bfloat16 lo = __float2bfloat16(v - __bfloat162float(hi));
    size_t o = ((size_t)l * 8 + c) * BTILE + n * BPAD + k;
    g_Uhi[o] = hi;
    g_Ulo[o] = lo;
}

// ---------------------------------------------------------------------------
// Generic tiled fp32 GEMM: C[M,N] = A[M,K] @ B[K,N] (+ bias)
// ---------------------------------------------------------------------------
__global__ void __launch_bounds__(256)
gemm_tiled(const float* __restrict__ A, const float* __restrict__ B,
           const float* __restrict__ bias, float* __restrict__ C,
           int M, int N, int K)
{
    __shared__ float As[16][64];
    __shared__ float Bs[16][68];

    const int tid = threadIdx.x;
    const int tm = tid >> 4, tn = tid & 15;
    const size_t bm = (size_t)blockIdx.x * 64;
    const int bn = blockIdx.y * 64;

    const int ar = tid >> 2, ak = (tid & 3) << 2;
    const int brow = tid >> 4, bcol = (tid & 15) << 2;

    float acc[4][4];
#pragma unroll
    for (int i = 0; i < 4; ++i)
#pragma unroll
        for (int j = 0; j < 4; ++j) acc[i][j] = 0.f;

    for (int k0 = 0; k0 < K; k0 += 16) {
        float4 av = *(const float4*)(A + (bm + ar) * (size_t)K + k0 + ak);
        As[ak + 0][ar] = av.x; As[ak + 1][ar] = av.y;
        As[ak + 2][ar] = av.z; As[ak + 3][ar] = av.w;

        float4 bv = make_float4(0.f, 0.f, 0.f, 0.f);
        if (bn + bcol < N)
            bv = *(const float4*)(B + (size_t)(k0 + brow) * N + bn + bcol);
        *(float4*)&Bs[brow][bcol] = bv;
        __syncthreads();

#pragma unroll
        for (int k = 0; k < 16; ++k) {
            float4 a = *(const float4*)&As[k][tm << 2];
            float4 b = *(const float4*)&Bs[k][tn << 2];
            acc[0][0] = fmaf(a.x, b.x, acc[0][0]); acc[0][1] = fmaf(a.x, b.y, acc[0][1]);
            acc[0][2] = fmaf(a.x, b.z, acc[0][2]); acc[0][3] = fmaf(a.x, b.w, acc[0][3]);
            acc[1][0] = fmaf(a.y, b.x, acc[1][0]); acc[1][1] = fmaf(a.y, b.y, acc[1][1]);
            acc[1][2] = fmaf(a.y, b.z, acc[1][2]); acc[1][3] = fmaf(a.y, b.w, acc[1][3]);
            acc[2][0] = fmaf(a.z, b.x, acc[2][0]); acc[2][1] = fmaf(a.z, b.y, acc[2][1]);
            acc[2][2] = fmaf(a.z, b.z, acc[2][2]); acc[2][3] = fmaf(a.z, b.w, acc[2][3]);
            acc[3][0] = fmaf(a.w, b.x, acc[3][0]); acc[3][1] = fmaf(a.w, b.y, acc[3][1]);
            acc[3][2] = fmaf(a.w, b.z, acc[3][2]); acc[3][3] = fmaf(a.w, b.w, acc[3][3]);
        }
        __syncthreads();
    }

#pragma unroll
    for (int i = 0; i < 4; ++i) {
        size_t row = bm + (tm << 2) + i;
#pragma unroll
        for (int j = 0; j < 4; ++j) {
            int colj = bn + (tn << 2) + j;
            if (colj < N) {
                float v = acc[i][j];
                if (bias) v += bias[colj];
                C[row * (size_t)N + colj] = v;
            }
        }
    }
}

__device__ __forceinline__ float sigmoidf_(float x)
{
    return __fdividef(1.f, 1.f + __expf(-x));
}
__device__ __forceinline__ float tanhf_(float x)
{
    return __fdividef(2.f, 1.f + __expf(-2.f * x)) - 1.f;
}

// ---------------------------------------------------------------------------
// HMMA recurrent kernel. 128 CTAs (16 groups x cluster-of-8), 128 threads.
// Group = 16 batch rows; CTA c owns 32 hidden cols (k-tiles 2c, 2c+1 of A)
// and gate cols {c*32+j, 256+c*32+j, 512+c*32+j}.
// Per step: D[16,96] = Ahi@Bhi + Alo@Bhi + Ahi@Blo via mma.sync m16n8k16.
// Warp w owns hidden cols 8w..8w+7 (3 n-tiles: z, r, c). Epilogue thread
// owns rows {lane>>2, +8} x cols {8w+2(lane&3), +1}; old h stays in regs.
// h_{t+1} published as bf16 hi/lo A-tile image to an L2 double buffer,
// cluster barrier, then linear 24KB reload into SMEM A tiles.
//
// SMEM: A [prec 2][ktile 16][16 rows][24 cols bf16] (48B row stride),
//       B hi/lo [96 n][264 k] (528B row stride). Both ldmatrix-conflict-free.
// ---------------------------------------------------------------------------
#define A_BYTES  24576                    // 2 * 16 * 768
#define B_BYTES  (BTILE * 2)              // 50688 per precision
#define RNN_SMEM (A_BYTES + 2 * B_BYTES)  // 125952

__global__ void __cluster_dims__(8, 1, 1) __launch_bounds__(128, 1)
rnn_hmma(const __nv_bfloat16* __restrict__ Uhi8,   // g_Uhi + l*8*BTILE
         const __nv_bfloat16* __restrict__ Ulo8,
         const float* __restrict__ wx,
         float* __restrict__ out_x,
         float* __restrict__ hT_out,
         __nv_bfloat16* __restrict__ hx)
{
    extern __shared__ char sm[];
    char* sA  = sm;                       // A image (hi at 0, lo at 12288)
    char* sBh = sm + A_BYTES;
    char* sBl = sBh + B_BYTES;

    const int c  = blockIdx.x & 7;
    const int g  = blockIdx.x >> 3;
    const int tid = threadIdx.x;
    const int w = tid >> 5, lane = tid & 31;

    // Load stationary B tiles; zero A tiles.
    {
        const uint4* s0 = (const uint4*)(Uhi8 + (size_t)c * BTILE);
        const uint4* s1 = (const uint4*)(Ulo8 + (size_t)c * BTILE);
        uint4* d0 = (uint4*)sBh;
        uint4* d1 = (uint4*)sBl;
        for (int i = tid; i < B_BYTES / 16; i += 128) { d0[i] = s0[i]; d1[i] = s1[i]; }
        uint4 z4 = make_uint4(0u, 0u, 0u, 0u);
        uint4* a4 = (uint4*)sA;
        for (int i = tid; i < A_BYTES / 16; i += 128) a4[i] = z4;
    }
    __syncthreads();

    // ldmatrix lane offsets
    const uint32_t sAu  = smem_u32(sA);
    const uint32_t sBhu = smem_u32(sBh);
    const uint32_t sBlu = smem_u32(sBl);
    const int q = lane >> 3, rr = lane & 7;
    const uint32_t aoff = (uint32_t)(((q & 1) * 8 + rr) * 48 + (q >> 1) * 16);
    const int bl2 = lane & 15;
    const uint32_t boff = (uint32_t)((bl2 & 7) * 528 + (bl2 >> 3) * 16);

    // epilogue ownership
    const int r1 = lane >> 2;                       // rows r1, r1+8
    const int coll = (w << 3) + ((lane & 3) << 1);  // local hidden col (even)
    const int hidg = (c << 5) + coll;               // global hidden col
    const size_t brow1 = (size_t)(g * 16 + r1);
    const size_t brow2 = brow1 + 8;

    // publish offsets into the A-tile image
    const int kt = hidg >> 4, kin = hidg & 15;
    const uint32_t po1 = (uint32_t)(kt * 768 + r1 * 48 + kin * 2);
    const uint32_t po2 = po1 + 8 * 48;

    // B row bases for this warp's 3 gate tiles
    const uint32_t bz = (uint32_t)((w << 3) * 528);
    const uint32_t br = bz + 32 * 528;
    const uint32_t bc = bz + 64 * 528;

    float hp[4] = {0.f, 0.f, 0.f, 0.f};            // old h (fp32, in regs)

    for (int t = 0; t < SEQ; ++t) {
        // ---- wx prefetch ----
        float2 wxv[3][2];
        {
            const float* p1 = wx + (brow1 * SEQ + t) * G3 + hidg;
            const float* p2 = wx + (brow2 * SEQ + t) * G3 + hidg;
            wxv[0][0] = *(const float2*)(p1);       wxv[0][1] = *(const float2*)(p2);
            wxv[1][0] = *(const float2*)(p1 + 256); wxv[1][1] = *(const float2*)(p2 + 256);
            wxv[2][0] = *(const float2*)(p1 + 512); wxv[2][1] = *(const float2*)(p2 + 512);
        }

        // ---- MMA: D[16,96] over k=256, 3 precision passes ----
        float dz[4] = {0.f, 0.f, 0.f, 0.f};
        float dr[4] = {0.f, 0.f, 0.f, 0.f};
        float dc[4] = {0.f, 0.f, 0.f, 0.f};
#pragma unroll
        for (int ktl = 0; ktl < 16; ++ktl) {
            uint32_t ah[4], al[4];
            const uint32_t ab = sAu + (uint32_t)(ktl * 768) + aoff;
            LDSM4(ah, ab);
            LDSM4(al, ab + 12288);
            const uint32_t ko = (uint32_t)(ktl * 32) + boff;

            uint32_t bh[2], blo[2];
            LDSM2(bh,  sBhu + bz + ko);
            LDSM2(blo, sBlu + bz + ko);
            MMA16816(dz, ah, bh);
            MMA16816(dz, al, bh);
            MMA16816(dz, ah, blo);

            LDSM2(bh,  sBhu + br + ko);
            LDSM2(blo, sBlu + br + ko);
            MMA16816(dr, ah, bh);
            MMA16816(dr, al, bh);
            MMA16816(dr, ah, blo);

            LDSM2(bh,  sBhu + bc + ko);
            LDSM2(blo, sBlu + bc + ko);
            MMA16816(dc, ah, bh);
            MMA16816(dc, al, bh);
            MMA16816(dc, ah, blo);
        }

        // ---- gates + h update (exact fp32) ----
        // D reg i: 0=(r1,col0) 1=(r1,col1) 2=(r2,col0) 3=(r2,col1)
        float hn[4];
#pragma unroll
        for (int i = 0; i < 4; ++i) {
            const int rs = i >> 1;                  // 0 -> row1, 1 -> row2
            const float wzv = (i & 1) ? wxv[0][rs].y : wxv[0][rs].x;
            const float wrv = (i & 1) ? wxv[1][rs].y : wxv[1][rs].x;
            const float wcv = (i & 1) ? wxv[2][rs].y : wxv[2][rs].x;
            const float z  = sigmoidf_(wzv + dz[i]);
            const float rg = sigmoidf_(wrv + dr[i]);
            const float cc = tanhf_(wcv + rg * dc[i]);
            hn[i] = z * hp[i] + (1.f - z) * cc;
            hp[i] = hn[i];
        }

        // ---- outputs ----
        {
            float* o1 = out_x + (brow1 * SEQ + t) * HID + hidg;
            float* o2 = out_x + (brow2 * SEQ + t) * HID + hidg;
            *(float2*)o1 = make_float2(hn[0], hn[1]);
            *(float2*)o2 = make_float2(hn[2], hn[3]);
            if (t == SEQ - 1) {
                *(float2*)(hT_out + brow1 * 512 + hidg) = make_float2(hn[0], hn[1]);
                *(float2*)(hT_out + brow2 * 512 + hidg) = make_float2(hn[2], hn[3]);
            }
        }

        // ---- publish h_{t+1} as bf16 hi/lo A-image ----
        {
            const int nb = (t + 1) & 1;
            char* ex = (char*)hx + (size_t)(nb * 16 + g) * A_BYTES;
            uint32_t hw[2], lw[2];
#pragma unroll
            for (int s = 0; s < 2; ++s) {
                __nv_bfloat16 h0 = __float2bfloat16(hn[2*s]);
                __nv_bfloat16 h1 = __float2bfloat16(hn[2*s+1]);
                __nv_bfloat16 l0 = __float2bfloat16(hn[2*s]   - __bfloat162float(h0));
                __nv_bfloat16 l1 = __float2bfloat16(hn[2*s+1] - __bfloat162float(h1));
                hw[s] = (uint32_t)__bfloat16_as_ushort(h0) |
                        ((uint32_t)__bfloat16_as_ushort(h1) << 16);
                lw[s] = (uint32_t)__bfloat16_as_ushort(l0) |
                        ((uint32_t)__bfloat16_as_ushort(l1) << 16);
            }
            *(uint32_t*)(ex + po1)         = hw[0];
            *(uint32_t*)(ex + po2)         = hw[1];
            *(uint32_t*)(ex + 12288 + po1) = lw[0];
            *(uint32_t*)(ex + 12288 + po2) = lw[1];
        }

        // ---- cluster barrier (release/acquire over global) ----
        asm volatile("barrier.cluster.arrive.aligned;" ::: "memory");
        asm volatile("barrier.cluster.wait.aligned;" ::: "memory");

        // ---- reload full A image (linear 24KB copy) ----
        {
            const int nb = (t + 1) & 1;
            const uint4* src = (const uint4*)((const char*)hx +
                                              (size_t)(nb * 16 + g) * A_BYTES);
            uint4* dst = (uint4*)sA;
#pragma unroll
            for (int i = 0; i < 12; ++i)
                dst[tid + 128 * i] = src[tid + 128 * i];
        }
        __syncthreads();
    }
}

// ---------------------------------------------------------------------------
// Launch
// ---------------------------------------------------------------------------
extern "C" void kernel_launch(void* const* d_in, const int* in_sizes, int n_in,
                              void* d_out, int out_size)
{
    const float* x   = (const float*)d_in[0];
    const float* Wd  = (const float*)d_in[1];
    const float* Wdg = (const float*)d_in[2];
    const float* Wo  = (const float*)d_in[3];
    const float* Wog = (const float*)d_in[4];
    const float* Ud  = (const float*)d_in[5];
    const float* Udg = (const float*)d_in[6];
    const float* Uo  = (const float*)d_in[7];
    const float* Uog = (const float*)d_in[8];
    const float* bb  = (const float*)d_in[9];
    float* out = (float*)d_out;

    float *pT, *pWX, *pX1, *pP, *pQ, *pPu, *pQu, *pUeff;
    __nv_bfloat16 *pUhi, *pUlo, *pHX;
    cudaGetSymbolAddress((void**)&pT,    g_t_buf);
    cudaGetSymbolAddress((void**)&pWX,   g_wx_buf);
    cudaGetSymbolAddress((void**)&pX1,   g_x1);
    cudaGetSymbolAddress((void**)&pP,    g_P);
    cudaGetSymbolAddress((void**)&pQ,    g_Q);
    cudaGetSymbolAddress((void**)&pPu,   g_Pu);
    cudaGetSymbolAddress((void**)&pQu,   g_Qu);
    cudaGetSymbolAddress((void**)&pUeff, g_Ueff);
    cudaGetSymbolAddress((void**)&pUhi,  g_Uhi);
    cudaGetSymbolAddress((void**)&pUlo,  g_Ulo);
    cudaGetSymbolAddress((void**)&pHX,   g_hx);

    cudaFuncSetAttribute(rnn_hmma, cudaFuncAttributeMaxDynamicSharedMemorySize,
                         RNN_SMEM);

    // 1. pack low-rank factors
    pack_kernel<<<(LAYERS * RANKSUM * G3 + 255) / 256, 256>>>(Wd, Wdg, Wo, Wog,
                                                              Ud, Udg, Uo, Uog);
    // 2. dense recurrent weights: Ueff[l] = Pu[l] @ Qu[l]
    for (int l = 0; l < LAYERS; ++l)
        gemm_tiled<<<dim3(HID / 64, G3 / 64), 256>>>(
            pPu + (size_t)l * HID * RANKSUM, pQu + (size_t)l * RANKSUM * G3,
            nullptr, pUeff + (size_t)l * HID * G3, HID, G3, RANKSUM);
    // 3. bf16 hi/lo split into B-operand layout
    split_u<<<(LAYERS * 8 * 96 * 256 + 255) / 256, 256>>>();

    const size_t OUT0 = (size_t)ROWS * HID;

    for (int l = 0; l < LAYERS; ++l) {
        const float* xin = (l == 0) ? x : pX1;
        gemm_tiled<<<dim3(ROWS / 64, 2), 256>>>(
            xin, pP + (size_t)l * NIN * RANKSUM, nullptr, pT, ROWS, RANKSUM, NIN);
        gemm_tiled<<<dim3(ROWS / 64, G3 / 64), 256>>>(
            pT, pQ + (size_t)l * RANKSUM * G3, bb + l * G3, pWX, ROWS, G3, RANKSUM);
        float* ox = (l == LAYERS - 1) ? out : pX1;
        rnn_hmma<<<128, 128, RNN_SMEM>>>(
            pUhi + (size_t)l * 8 * BTILE, pUlo + (size_t)l * 8 * BTILE,
            pWX, ox, out + OUT0 + l * HID, pHX);
    }
}

// round 7
// speedup vs baseline: 1.4926x; 1.1187x over previous
#include <cuda_runtime.h>
#include <cuda_bf16.h>
#include <cstdint>
#include <cstddef>

// ---------------------------------------------------------------------------
// Problem constants
// ---------------------------------------------------------------------------
#define BATCH   256
#define SEQ     512
#define NIN     256
#define HID     256
#define G3      768
#define LAYERS  2
#define ROWS    (BATCH*SEQ)
#define RANKSUM 96

// ---------------------------------------------------------------------------
// Static device scratch (no cudaMalloc allowed)
// ---------------------------------------------------------------------------
__device__ float g_t_buf[(size_t)ROWS * RANKSUM];
__device__ float g_wx_buf[(size_t)ROWS * G3];
__device__ float g_x1[(size_t)ROWS * HID];
__device__ float g_P [LAYERS * NIN * RANKSUM];
__device__ float g_Q [LAYERS * RANKSUM * G3];
__device__ float g_Pu[LAYERS * HID * RANKSUM];
__device__ float g_Qu[LAYERS * RANKSUM * G3];
__device__ float g_Ueff[LAYERS * HID * G3];

// U as bf16 hi/lo in B-operand layout: per (layer, cta): [96 n][264 k-padded]
#define BPAD  264                         // 528 bytes per row (bank step 4)
#define BTILE (96 * BPAD)                 // elems per (l, c) per precision
__device__ __nv_bfloat16 g_Uhi[(size_t)LAYERS * 8 * BTILE];
__device__ __nv_bfloat16 g_Ulo[(size_t)LAYERS * 8 * BTILE];

// h exchange: A-tile images [buf 2][group 16][hi 12288B | lo 12288B]
__device__ __nv_bfloat16 g_hx[2 * 16 * 2 * 6144];

// ---------------------------------------------------------------------------
// PTX helpers (baseline-target-safe: ldmatrix + mma.sync only)
// ---------------------------------------------------------------------------
__device__ __forceinline__ uint32_t smem_u32(const void* p)
{
    uint32_t a;
    asm("{ .reg .u64 t; cvta.to.shared.u64 t, %1; cvt.u32.u64 %0, t; }"
        : "=r"(a) : "l"(p));
    return a;
}

#define LDSM4(R, addr) \
    asm volatile("ldmatrix.sync.aligned.m8n8.x4.shared.b16 {%0,%1,%2,%3}, [%4];" \
        : "=r"((R)[0]), "=r"((R)[1]), "=r"((R)[2]), "=r"((R)[3]) : "r"(addr))
#define MMA16816(D, A, B) \
    asm volatile("mma.sync.aligned.m16n8k16.row.col.f32.bf16.bf16.f32 " \
        "{%0,%1,%2,%3}, {%4,%5,%6,%7}, {%8,%9}, {%0,%1,%2,%3};" \
        : "+f"((D)[0]), "+f"((D)[1]), "+f"((D)[2]), "+f"((D)[3]) \
        : "r"((A)[0]), "r"((A)[1]), "r"((A)[2]), "r"((A)[3]), \
          "r"((B)[0]), "r"((B)[1]))

// ---------------------------------------------------------------------------
// Pack kernel: concatenate low-rank factors
// ---------------------------------------------------------------------------
__global__ void pack_kernel(const float* __restrict__ Wd, const float* __restrict__ Wdg,
                            const float* __restrict__ Wo, const float* __restrict__ Wog,
                            const float* __restrict__ Ud, const float* __restrict__ Udg,
                            const float* __restrict__ Uo, const float* __restrict__ Uog)
{
    int idx = blockIdx.x * 256 + threadIdx.x;
    const int QN = LAYERS * RANKSUM * G3;
    const int PN = LAYERS * NIN * RANKSUM;
    if (idx < QN) {
        int l = idx / (RANKSUM * G3);
        int rem = idx - l * (RANKSUM * G3);
        int r = rem / G3, n = rem - r * G3;
        g_Q[idx]  = (r < 64) ? Wdg[(l*64 + r) * G3 + n] : Wog[(l*32 + (r-64)) * G3 + n];
        g_Qu[idx] = (r < 64) ? Udg[(l*64 + r) * G3 + n] : Uog[(l*32 + (r-64)) * G3 + n];
    }
    if (idx < PN) {
        int l = idx / (NIN * RANKSUM);
        int rem = idx - l * (NIN * RANKSUM);
        int k = rem / RANKSUM, j = rem - k * RANKSUM;
        g_P[idx]  = (j < 64) ? Wd[(l*NIN + k) * 64 + j] : Wo[(l*NIN + k) * 32 + (j-64)];
        g_Pu[idx] = (j < 64) ? Ud[(l*NIN + k) * 64 + j] : Uo[(l*NIN + k) * 32 + (j-64)];
    }
}

// ---------------------------------------------------------------------------
// Split Ueff into bf16 hi/lo in B-operand layout.
// ---------------------------------------------------------------------------
__global__ void split_u()
{
    int idx = blockIdx.x * 256 + threadIdx.x;
    if (idx >= LAYERS * 8 * 96 * 256) return;
    int k = idx & 255;
    int n = (idx >> 8) % 96;
    int c = (idx >> 8) / 96 % 8;
    int l = idx / (8 * 96 * 256);
    int gatecol = ((n >> 5) << 8) + (c << 5) + (n & 31);
    float v = g_Ueff[(size_t)l * HID * G3 + (size_t)k * G3 + gatecol];
    __nv_bfloat16 hi = __float2bfloat16(v);
    __nv_bfloat16 lo = __float2bfloat16(v - __bfloat162float(hi));
    size_t o = ((size_t)l * 8 + c) * BTILE + n * BPAD + k;
    g_Uhi[o] = hi;
    g_Ulo[o] = lo;
}

// ---------------------------------------------------------------------------
// Generic tiled fp32 GEMM: C[M,N] = A[M,K] @ B[K,N] (+ bias)
// ---------------------------------------------------------------------------
__global__ void __launch_bounds__(256)
gemm_tiled(const float* __restrict__ A, const float* __restrict__ B,
           const float* __restrict__ bias, float* __restrict__ C,
           int M, int N, int K)
{
    __shared__ float As[16][64];
    __shared__ float Bs[16][68];

    const int tid = threadIdx.x;
    const int tm = tid >> 4, tn = tid & 15;
    const size_t bm = (size_t)blockIdx.x * 64;
    const int bn = blockIdx.y * 64;

    const int ar = tid >> 2, ak = (tid & 3) << 2;
    const int brow = tid >> 4, bcol = (tid & 15) << 2;

    float acc[4][4];
#pragma unroll
    for (int i = 0; i < 4; ++i)
#pragma unroll
        for (int j = 0; j < 4; ++j) acc[i][j] = 0.f;

    for (int k0 = 0; k0 < K; k0 += 16) {
        float4 av = *(const float4*)(A + (bm + ar) * (size_t)K + k0 + ak);
        As[ak + 0][ar] = av.x; As[ak + 1][ar] = av.y;
        As[ak + 2][ar] = av.z; As[ak + 3][ar] = av.w;

        float4 bv = make_float4(0.f, 0.f, 0.f, 0.f);
        if (bn + bcol < N)
            bv = *(const float4*)(B + (size_t)(k0 + brow) * N + bn + bcol);
        *(float4*)&Bs[brow][bcol] = bv;
        __syncthreads();

#pragma unroll
        for (int k = 0; k < 16; ++k) {
            float4 a = *(const float4*)&As[k][tm << 2];
            float4 b = *(const float4*)&Bs[k][tn << 2];
            acc[0][0] = fmaf(a.x, b.x, acc[0][0]); acc[0][1] = fmaf(a.x, b.y, acc[0][1]);
            acc[0][2] = fmaf(a.x, b.z, acc[0][2]); acc[0][3] = fmaf(a.x, b.w, acc[0][3]);
            acc[1][0] = fmaf(a.y, b.x, acc[1][0]); acc[1][1] = fmaf(a.y, b.y, acc[1][1]);
            acc[1][2] = fmaf(a.y, b.z, acc[1][2]); acc[1][3] = fmaf(a.y, b.w, acc[1][3]);
            acc[2][0] = fmaf(a.z, b.x, acc[2][0]); acc[2][1] = fmaf(a.z, b.y, acc[2][1]);
            acc[2][2] = fmaf(a.z, b.z, acc[2][2]); acc[2][3] = fmaf(a.z, b.w, acc[2][3]);
            acc[3][0] = fmaf(a.w, b.x, acc[3][0]); acc[3][1] = fmaf(a.w, b.y, acc[3][1]);
            acc[3][2] = fmaf(a.w, b.z, acc[3][2]); acc[3][3] = fmaf(a.w, b.w, acc[3][3]);
        }
        __syncthreads();
    }

#pragma unroll
    for (int i = 0; i < 4; ++i) {
        size_t row = bm + (tm << 2) + i;
#pragma unroll
        for (int j = 0; j < 4; ++j) {
            int colj = bn + (tn << 2) + j;
            if (colj < N) {
                float v = acc[i][j];
                if (bias) v += bias[colj];
                C[row * (size_t)N + colj] = v;
            }
        }
    }
}

__device__ __forceinline__ float sigmoidf_(float x)
{
    return __fdividef(1.f, 1.f + __expf(-x));
}
__device__ __forceinline__ float tanhf_(float x)
{
    return __fdividef(2.f, 1.f + __expf(-2.f * x)) - 1.f;
}

// ---------------------------------------------------------------------------
// HMMA recurrent kernel v2: k-split, 8 warps (2/SMSP).
// 128 CTAs (16 groups x cluster-of-8), 256 threads.
// Warp w: kh = w>>2 (k-half: 8 ktiles), cg = w&3 (8 hidden cols).
// Per warp per ktl: 2 LDSM4 (A hi/lo) + 3 LDSM4 (B hi+lo fused per gate)
// + 9 MMA. kh=1 partials reduced through smem; kh=0 warps run the epilogue
// (identical ownership to R6).
// ---------------------------------------------------------------------------
#define A_BYTES  24576                    // 2 prec * 16 ktile * 768B
#define B_BYTES  (BTILE * 2)              // 50688 per precision
#define RED_BYTES (4 * 32 * 12 * 4)       // 6144
#define RNN_SMEM (A_BYTES + 2 * B_BYTES + RED_BYTES)   // 132096

__global__ void __cluster_dims__(8, 1, 1) __launch_bounds__(256, 1)
rnn_hmma(const __nv_bfloat16* __restrict__ Uhi8,
         const __nv_bfloat16* __restrict__ Ulo8,
         const float* __restrict__ wx,
         float* __restrict__ out_x,
         float* __restrict__ hT_out,
         __nv_bfloat16* __restrict__ hx)
{
    extern __shared__ char sm[];
    char* sA  = sm;                       // A image (hi at 0, lo at 12288)
    char* sBh = sm + A_BYTES;
    char* sBl = sBh + B_BYTES;
    float* red = (float*)(sBl + B_BYTES); // [cg 4][lane 32][12]

    const int c  = blockIdx.x & 7;
    const int g  = blockIdx.x >> 3;
    const int tid = threadIdx.x;
    const int w = tid >> 5, lane = tid & 31;
    const int kh = w >> 2;                // k-half
    const int cg = w & 3;                 // col group

    // Load stationary B tiles; zero A tiles.
    {
        const uint4* s0 = (const uint4*)(Uhi8 + (size_t)c * BTILE);
        const uint4* s1 = (const uint4*)(Ulo8 + (size_t)c * BTILE);
        uint4* d0 = (uint4*)sBh;
        uint4* d1 = (uint4*)sBl;
        for (int i = tid; i < B_BYTES / 16; i += 256) { d0[i] = s0[i]; d1[i] = s1[i]; }
        uint4 z4 = make_uint4(0u, 0u, 0u, 0u);
        uint4* a4 = (uint4*)sA;
        for (int i = tid; i < A_BYTES / 16; i += 256) a4[i] = z4;
    }
    __syncthreads();

    // ldmatrix lane offsets
    const uint32_t sAu  = smem_u32(sA);
    const uint32_t sBhu = smem_u32(sBh);
    const uint32_t sBlu = smem_u32(sBl);
    const int q = lane >> 3, rr = lane & 7;
    const uint32_t aoff = (uint32_t)(((q & 1) * 8 + rr) * 48 + (q >> 1) * 16);
    // fused B LDSM4: lane groups 0,1 -> Bhi (k0/k8); groups 2,3 -> Blo (k0/k8)
    const uint32_t bbase = ((q < 2) ? sBhu : sBlu)
                         + (uint32_t)(rr * 528 + (q & 1) * 16)
                         + (uint32_t)((cg << 3) * 528);
    const uint32_t bz = 0, br = 32 * 528, bc = 64 * 528;

    // epilogue ownership (kh == 0 warps only; identical to R6 w->cg)
    const int r1 = lane >> 2;
    const int coll = (cg << 3) + ((lane & 3) << 1);
    const int hidg = (c << 5) + coll;
    const size_t brow1 = (size_t)(g * 16 + r1);
    const size_t brow2 = brow1 + 8;
    const int kt = hidg >> 4, kin = hidg & 15;
    const uint32_t po1 = (uint32_t)(kt * 768 + r1 * 48 + kin * 2);
    const uint32_t po2 = po1 + 8 * 48;

    float hp[4] = {0.f, 0.f, 0.f, 0.f};

    for (int t = 0; t < SEQ; ++t) {
        // ---- wx prefetch (epilogue warps only) ----
        float2 wxv[3][2];
        if (kh == 0) {
            const float* p1 = wx + (brow1 * SEQ + t) * G3 + hidg;
            const float* p2 = wx + (brow2 * SEQ + t) * G3 + hidg;
            wxv[0][0] = *(const float2*)(p1);       wxv[0][1] = *(const float2*)(p2);
            wxv[1][0] = *(const float2*)(p1 + 256); wxv[1][1] = *(const float2*)(p2 + 256);
            wxv[2][0] = *(const float2*)(p1 + 512); wxv[2][1] = *(const float2*)(p2 + 512);
        }

        // ---- MMA over this warp's 8 k-tiles ----
        float dz[4] = {0.f, 0.f, 0.f, 0.f};
        float dr[4] = {0.f, 0.f, 0.f, 0.f};
        float dc[4] = {0.f, 0.f, 0.f, 0.f};
#pragma unroll
        for (int i = 0; i < 8; ++i) {
            const int ktl = (kh << 3) + i;
            uint32_t ah[4], al[4];
            const uint32_t ab = sAu + (uint32_t)(ktl * 768) + aoff;
            LDSM4(ah, ab);
            LDSM4(al, ab + 12288);
            const uint32_t ko = bbase + (uint32_t)(ktl * 32);

            uint32_t bf[4];
            LDSM4(bf, ko + bz);                  // regs 0,1 = hi; 2,3 = lo
            MMA16816(dz, ah, bf);
            MMA16816(dz, al, bf);
            MMA16816(dz, ah, bf + 2);

            LDSM4(bf, ko + br);
            MMA16816(dr, ah, bf);
            MMA16816(dr, al, bf);
            MMA16816(dr, ah, bf + 2);

            LDSM4(bf, ko + bc);
            MMA16816(dc, ah, bf);
            MMA16816(dc, al, bf);
            MMA16816(dc, ah, bf + 2);
        }

        // ---- 2-way k reduction through smem ----
        if (kh) {
            float* s = red + (cg * 32 + lane) * 12;
            *(float4*)(s + 0) = make_float4(dz[0], dz[1], dz[2], dz[3]);
            *(float4*)(s + 4) = make_float4(dr[0], dr[1], dr[2], dr[3]);
            *(float4*)(s + 8) = make_float4(dc[0], dc[1], dc[2], dc[3]);
        }
        __syncthreads();

        float hn[4];
        if (kh == 0) {
            const float* s = red + (cg * 32 + lane) * 12;
            const float4 vz = *(const float4*)(s + 0);
            const float4 vr = *(const float4*)(s + 4);
            const float4 vc = *(const float4*)(s + 8);
            dz[0] += vz.x; dz[1] += vz.y; dz[2] += vz.z; dz[3] += vz.w;
            dr[0] += vr.x; dr[1] += vr.y; dr[2] += vr.z; dr[3] += vr.w;
            dc[0] += vc.x; dc[1] += vc.y; dc[2] += vc.z; dc[3] += vc.w;

            // gates + h update
#pragma unroll
            for (int i = 0; i < 4; ++i) {
                const int rs = i >> 1;
                const float wzv = (i & 1) ? wxv[0][rs].y : wxv[0][rs].x;
                const float wrv = (i & 1) ? wxv[1][rs].y : wxv[1][rs].x;
                const float wcv = (i & 1) ? wxv[2][rs].y : wxv[2][rs].x;
                const float z  = sigmoidf_(wzv + dz[i]);
                const float rg = sigmoidf_(wrv + dr[i]);
                const float cc = tanhf_(wcv + rg * dc[i]);
                hn[i] = z * hp[i] + (1.f - z) * cc;
                hp[i] = hn[i];
            }

            // publish h_{t+1} bf16 hi/lo to the exchange buffer
            const int nb = (t + 1) & 1;
            char* ex = (char*)hx + (size_t)(nb * 16 + g) * A_BYTES;
            uint32_t hw[2], lw[2];
#pragma unroll
            for (int s2 = 0; s2 < 2; ++s2) {
                __nv_bfloat16 h0 = __float2bfloat16(hn[2*s2]);
                __nv_bfloat16 h1 = __float2bfloat16(hn[2*s2+1]);
                __nv_bfloat16 l0 = __float2bfloat16(hn[2*s2]   - __bfloat162float(h0));
                __nv_bfloat16 l1 = __float2bfloat16(hn[2*s2+1] - __bfloat162float(h1));
                hw[s2] = (uint32_t)__bfloat16_as_ushort(h0) |
                         ((uint32_t)__bfloat16_as_ushort(h1) << 16);
                lw[s2] = (uint32_t)__bfloat16_as_ushort(l0) |
                         ((uint32_t)__bfloat16_as_ushort(l1) << 16);
            }
            *(uint32_t*)(ex + po1)         = hw[0];
            *(uint32_t*)(ex + po2)         = hw[1];
            *(uint32_t*)(ex + 12288 + po1) = lw[0];
            *(uint32_t*)(ex + 12288 + po2) = lw[1];
        }

        // ---- cluster barrier ----
        asm volatile("barrier.cluster.arrive.aligned;" ::: "memory");

        // out_x / hT stores off the critical path
        if (kh == 0) {
            float* o1 = out_x + (brow1 * SEQ + t) * HID + hidg;
            float* o2 = out_x + (brow2 * SEQ + t) * HID + hidg;
            *(float2*)o1 = make_float2(hn[0], hn[1]);
            *(float2*)o2 = make_float2(hn[2], hn[3]);
            if (t == SEQ - 1) {
                *(float2*)(hT_out + brow1 * 512 + hidg) = make_float2(hn[0], hn[1]);
                *(float2*)(hT_out + brow2 * 512 + hidg) = make_float2(hn[2], hn[3]);
            }
        }

        asm volatile("barrier.cluster.wait.aligned;" ::: "memory");

        // ---- reload full A image (linear 24KB copy, 256 threads) ----
        {
            const int nb = (t + 1) & 1;
            const uint4* src = (const uint4*)((const char*)hx +
                                              (size_t)(nb * 16 + g) * A_BYTES);
            uint4* dst = (uint4*)sA;
#pragma unroll
            for (int i = 0; i < 6; ++i)
                dst[tid + 256 * i] = src[tid + 256 * i];
        }
        __syncthreads();
    }
}

// ---------------------------------------------------------------------------
// Launch
// ---------------------------------------------------------------------------
extern "C" void kernel_launch(void* const* d_in, const int* in_sizes, int n_in,
                              void* d_out, int out_size)
{
    const float* x   = (const float*)d_in[0];
    const float* Wd  = (const float*)d_in[1];
    const float* Wdg = (const float*)d_in[2];
    const float* Wo  = (const float*)d_in[3];
    const float* Wog = (const float*)d_in[4];
    const float* Ud  = (const float*)d_in[5];
    const float* Udg = (const float*)d_in[6];
    const float* Uo  = (const float*)d_in[7];
    const float* Uog = (const float*)d_in[8];
    const float* bb  = (const float*)d_in[9];
    float* out = (float*)d_out;

    float *pT, *pWX, *pX1, *pP, *pQ, *pPu, *pQu, *pUeff;
    __nv_bfloat16 *pUhi, *pUlo, *pHX;
    cudaGetSymbolAddress((void**)&pT,    g_t_buf);
    cudaGetSymbolAddress((void**)&pWX,   g_wx_buf);
    cudaGetSymbolAddress((void**)&pX1,   g_x1);
    cudaGetSymbolAddress((void**)&pP,    g_P);
    cudaGetSymbolAddress((void**)&pQ,    g_Q);
    cudaGetSymbolAddress((void**)&pPu,   g_Pu);
    cudaGetSymbolAddress((void**)&pQu,   g_Qu);
    cudaGetSymbolAddress((void**)&pUeff, g_Ueff);
    cudaGetSymbolAddress((void**)&pUhi,  g_Uhi);
    cudaGetSymbolAddress((void**)&pUlo,  g_Ulo);
    cudaGetSymbolAddress((void**)&pHX,   g_hx);

    cudaFuncSetAttribute(rnn_hmma, cudaFuncAttributeMaxDynamicSharedMemorySize,
                         RNN_SMEM);

    pack_kernel<<<(LAYERS * RANKSUM * G3 + 255) / 256, 256>>>(Wd, Wdg, Wo, Wog,
                                                              Ud, Udg, Uo, Uog);
    for (int l = 0; l < LAYERS; ++l)
        gemm_tiled<<<dim3(HID / 64, G3 / 64), 256>>>(
            pPu + (size_t)l * HID * RANKSUM, pQu + (size_t)l * RANKSUM * G3,
            nullptr, pUeff + (size_t)l * HID * G3, HID, G3, RANKSUM);
    split_u<<<(LAYERS * 8 * 96 * 256 + 255) / 256, 256>>>();

    const size_t OUT0 = (size_t)ROWS * HID;

    for (int l = 0; l < LAYERS; ++l) {
        const float* xin = (l == 0) ? x : pX1;
        gemm_tiled<<<dim3(ROWS / 64, 2), 256>>>(
            xin, pP + (size_t)l * NIN * RANKSUM, nullptr, pT, ROWS, RANKSUM, NIN);
        gemm_tiled<<<dim3(ROWS / 64, G3 / 64), 256>>>(
            pT, pQ + (size_t)l * RANKSUM * G3, bb + l * G3, pWX, ROWS, G3, RANKSUM);
        float* ox = (l == LAYERS - 1) ? out : pX1;
        rnn_hmma<<<128, 256, RNN_SMEM>>>(
            pUhi + (size_t)l * 8 * BTILE, pUlo + (size_t)l * 8 * BTILE,
            pWX, ox, out + OUT0 + l * HID, pHX);
    }
}

// round 8
// speedup vs baseline: 1.6128x; 1.0805x over previous
#include <cuda_runtime.h>
#include <cuda_bf16.h>
#include <cstdint>
#include <cstddef>

// ---------------------------------------------------------------------------
// Problem constants
// ---------------------------------------------------------------------------
#define BATCH   256
#define SEQ     512
#define NIN     256
#define HID     256
#define G3      768
#define LAYERS  2
#define ROWS    (BATCH*SEQ)
#define RANKSUM 96

// ---------------------------------------------------------------------------
// Static device scratch (no cudaMalloc allowed)
// ---------------------------------------------------------------------------
__device__ float g_t_buf[(size_t)ROWS * RANKSUM];
__device__ float g_wx_buf[(size_t)ROWS * G3];
__device__ float g_x1[(size_t)ROWS * HID];
__device__ float g_P [LAYERS * NIN * RANKSUM];
__device__ float g_Q [LAYERS * RANKSUM * G3];
__device__ float g_Pu[LAYERS * HID * RANKSUM];
__device__ float g_Qu[LAYERS * RANKSUM * G3];
__device__ float g_Ueff[LAYERS * HID * G3];

// U as bf16 hi/lo in B-operand layout: per (layer, cta): [96 n][264 k-padded]
#define BPAD  264                         // 528 bytes per row (bank step 4)
#define BTILE (96 * BPAD)                 // elems per (l, c) per precision
__device__ __nv_bfloat16 g_Uhi[(size_t)LAYERS * 8 * BTILE];
__device__ __nv_bfloat16 g_Ulo[(size_t)LAYERS * 8 * BTILE];

// h exchange: A-tile images [buf 2][group 16][hi 12288B | lo 12288B]
__device__ __nv_bfloat16 g_hx[2 * 16 * 2 * 6144];

// ---------------------------------------------------------------------------
// PTX helpers (baseline-target-safe: ldmatrix + mma.sync only)
// ---------------------------------------------------------------------------
__device__ __forceinline__ uint32_t smem_u32(const void* p)
{
    uint32_t a;
    asm("{ .reg .u64 t; cvta.to.shared.u64 t, %1; cvt.u32.u64 %0, t; }"
        : "=r"(a) : "l"(p));
    return a;
}

#define LDSM4(R, addr) \
    asm volatile("ldmatrix.sync.aligned.m8n8.x4.shared.b16 {%0,%1,%2,%3}, [%4];" \
        : "=r"((R)[0]), "=r"((R)[1]), "=r"((R)[2]), "=r"((R)[3]) : "r"(addr))
#define MMA16816(D, A, B) \
    asm volatile("mma.sync.aligned.m16n8k16.row.col.f32.bf16.bf16.f32 " \
        "{%0,%1,%2,%3}, {%4,%5,%6,%7}, {%8,%9}, {%0,%1,%2,%3};" \
        : "+f"((D)[0]), "+f"((D)[1]), "+f"((D)[2]), "+f"((D)[3]) \
        : "r"((A)[0]), "r"((A)[1]), "r"((A)[2]), "r"((A)[3]), \
          "r"((B)[0]), "r"((B)[1]))

// ---------------------------------------------------------------------------
// Pack kernel: concatenate low-rank factors
// ---------------------------------------------------------------------------
__global__ void pack_kernel(const float* __restrict__ Wd, const float* __restrict__ Wdg,
                            const float* __restrict__ Wo, const float* __restrict__ Wog,
                            const float* __restrict__ Ud, const float* __restrict__ Udg,
                            const float* __restrict__ Uo, const float* __restrict__ Uog)
{
    int idx = blockIdx.x * 256 + threadIdx.x;
    const int QN = LAYERS * RANKSUM * G3;
    const int PN = LAYERS * NIN * RANKSUM;
    if (idx < QN) {
        int l = idx / (RANKSUM * G3);
        int rem = idx - l * (RANKSUM * G3);
        int r = rem / G3, n = rem - r * G3;
        g_Q[idx]  = (r < 64) ? Wdg[(l*64 + r) * G3 + n] : Wog[(l*32 + (r-64)) * G3 + n];
        g_Qu[idx] = (r < 64) ? Udg[(l*64 + r) * G3 + n] : Uog[(l*32 + (r-64)) * G3 + n];
    }
    if (idx < PN) {
        int l = idx / (NIN * RANKSUM);
        int rem = idx - l * (NIN * RANKSUM);
        int k = rem / RANKSUM, j = rem - k * RANKSUM;
        g_P[idx]  = (j < 64) ? Wd[(l*NIN + k) * 64 + j] : Wo[(l*NIN + k) * 32 + (j-64)];
        g_Pu[idx] = (j < 64) ? Ud[(l*NIN + k) * 64 + j] : Uo[(l*NIN + k) * 32 + (j-64)];
    }
}

// ---------------------------------------------------------------------------
// Split Ueff into bf16 hi/lo in B-operand layout.
// ---------------------------------------------------------------------------
__global__ void split_u()
{
    int idx = blockIdx.x * 256 + threadIdx.x;
    if (idx >= LAYERS * 8 * 96 * 256) return;
    int k = idx & 255;
    int n = (idx >> 8) % 96;
    int c = (idx >> 8) / 96 % 8;
    int l = idx / (8 * 96 * 256);
    int gatecol = ((n >> 5) << 8) + (c << 5) + (n & 31);
    float v = g_Ueff[(size_t)l * HID * G3 + (size_t)k * G3 + gatecol];
    __nv_bfloat16 hi = __float2bfloat16(v);
    __nv_bfloat16 lo = __float2bfloat16(v - __bfloat162float(hi));
    size_t o = ((size_t)l * 8 + c) * BTILE + n * BPAD + k;
    g_Uhi[o] = hi;
    g_Ulo[o] = lo;
}

// ---------------------------------------------------------------------------
// Generic tiled fp32 GEMM: C[M,N] = A[M,K] @ B[K,N] (+ bias)
// ---------------------------------------------------------------------------
__global__ void __launch_bounds__(256)
gemm_tiled(const float* __restrict__ A, const float* __restrict__ B,
           const float* __restrict__ bias, float* __restrict__ C,
           int M, int N, int K)
{
    __shared__ float As[16][64];
    __shared__ float Bs[16][68];

    const int tid = threadIdx.x;
    const int tm = tid >> 4, tn = tid & 15;
    const size_t bm = (size_t)blockIdx.x * 64;
    const int bn = blockIdx.y * 64;

    const int ar = tid >> 2, ak = (tid & 3) << 2;
    const int brow = tid >> 4, bcol = (tid & 15) << 2;

    float acc[4][4];
#pragma unroll
    for (int i = 0; i < 4; ++i)
#pragma unroll
        for (int j = 0; j < 4; ++j) acc[i][j] = 0.f;

    for (int k0 = 0; k0 < K; k0 += 16) {
        float4 av = *(const float4*)(A + (bm + ar) * (size_t)K + k0 + ak);
        As[ak + 0][ar] = av.x; As[ak + 1][ar] = av.y;
        As[ak + 2][ar] = av.z; As[ak + 3][ar] = av.w;

        float4 bv = make_float4(0.f, 0.f, 0.f, 0.f);
        if (bn + bcol < N)
            bv = *(const float4*)(B + (size_t)(k0 + brow) * N + bn + bcol);
        *(float4*)&Bs[brow][bcol] = bv;
        __syncthreads();

#pragma unroll
        for (int k = 0; k < 16; ++k) {
            float4 a = *(const float4*)&As[k][tm << 2];
            float4 b = *(const float4*)&Bs[k][tn << 2];
            acc[0][0] = fmaf(a.x, b.x, acc[0][0]); acc[0][1] = fmaf(a.x, b.y, acc[0][1]);
            acc[0][2] = fmaf(a.x, b.z, acc[0][2]); acc[0][3] = fmaf(a.x, b.w, acc[0][3]);
            acc[1][0] = fmaf(a.y, b.x, acc[1][0]); acc[1][1] = fmaf(a.y, b.y, acc[1][1]);
            acc[1][2] = fmaf(a.y, b.z, acc[1][2]); acc[1][3] = fmaf(a.y, b.w, acc[1][3]);
            acc[2][0] = fmaf(a.z, b.x, acc[2][0]); acc[2][1] = fmaf(a.z, b.y, acc[2][1]);
            acc[2][2] = fmaf(a.z, b.z, acc[2][2]); acc[2][3] = fmaf(a.z, b.w, acc[2][3]);
            acc[3][0] = fmaf(a.w, b.x, acc[3][0]); acc[3][1] = fmaf(a.w, b.y, acc[3][1]);
            acc[3][2] = fmaf(a.w, b.z, acc[3][2]); acc[3][3] = fmaf(a.w, b.w, acc[3][3]);
        }
        __syncthreads();
    }

#pragma unroll
    for (int i = 0; i < 4; ++i) {
        size_t row = bm + (tm << 2) + i;
#pragma unroll
        for (int j = 0; j < 4; ++j) {
            int colj = bn + (tn << 2) + j;
            if (colj < N) {
                float v = acc[i][j];
                if (bias) v += bias[colj];
                C[row * (size_t)N + colj] = v;
            }
        }
    }
}

__device__ __forceinline__ float sigmoidf_(float x)
{
    return __fdividef(1.f, 1.f + __expf(-x));
}
__device__ __forceinline__ float tanhf_(float x)
{
    return __fdividef(2.f, 1.f + __expf(-2.f * x)) - 1.f;
}

// ---------------------------------------------------------------------------
// HMMA recurrent kernel v3: 4-way k-split (512 threads, 4 warps/SMSP in MMA)
// + wx prefetched one step ahead (DRAM latency & straggler variance hidden).
// 128 CTAs (16 groups x cluster-of-8).
// Warp w: kq = w>>2 (k-quarter: 4 ktiles), cg = w&3 (8 hidden cols).
// kq>0 partials reduced through smem; kq=0 warps (1/SMSP) run the epilogue.
// ---------------------------------------------------------------------------
#define A_BYTES  24576                    // 2 prec * 16 ktile * 768B
#define B_BYTES  (BTILE * 2)              // 50688 per precision
#define RED_BYTES (3 * 4 * 32 * 12 * 4)   // 18432
#define RNN_SMEM (A_BYTES + 2 * B_BYTES + RED_BYTES)   // 144384

__global__ void __cluster_dims__(8, 1, 1) __launch_bounds__(512, 1)
rnn_hmma(const __nv_bfloat16* __restrict__ Uhi8,
         const __nv_bfloat16* __restrict__ Ulo8,
         const float* __restrict__ wx,
         float* __restrict__ out_x,
         float* __restrict__ hT_out,
         __nv_bfloat16* __restrict__ hx)
{
    extern __shared__ char sm[];
    char* sA  = sm;                       // A image (hi at 0, lo at 12288)
    char* sBh = sm + A_BYTES;
    char* sBl = sBh + B_BYTES;
    float* red = (float*)(sBl + B_BYTES); // [3 src][cg 4][lane 32][12]

    const int c  = blockIdx.x & 7;
    const int g  = blockIdx.x >> 3;
    const int tid = threadIdx.x;
    const int w = tid >> 5, lane = tid & 31;
    const int kq = w >> 2;                // k-quarter 0..3
    const int cg = w & 3;                 // col group

    // Load stationary B tiles; zero A tiles.
    {
        const uint4* s0 = (const uint4*)(Uhi8 + (size_t)c * BTILE);
        const uint4* s1 = (const uint4*)(Ulo8 + (size_t)c * BTILE);
        uint4* d0 = (uint4*)sBh;
        uint4* d1 = (uint4*)sBl;
        for (int i = tid; i < B_BYTES / 16; i += 512) { d0[i] = s0[i]; d1[i] = s1[i]; }
        uint4 z4 = make_uint4(0u, 0u, 0u, 0u);
        uint4* a4 = (uint4*)sA;
        for (int i = tid; i < A_BYTES / 16; i += 512) a4[i] = z4;
    }
    __syncthreads();

    // ldmatrix lane offsets
    const uint32_t sAu  = smem_u32(sA);
    const uint32_t sBhu = smem_u32(sBh);
    const uint32_t sBlu = smem_u32(sBl);
    const int q = lane >> 3, rr = lane & 7;
    const uint32_t aoff = (uint32_t)(((q & 1) * 8 + rr) * 48 + (q >> 1) * 16);
    // fused B LDSM4: lane groups 0,1 -> Bhi (k0/k8); groups 2,3 -> Blo (k0/k8)
    const uint32_t bbase = ((q < 2) ? sBhu : sBlu)
                         + (uint32_t)(rr * 528 + (q & 1) * 16)
                         + (uint32_t)((cg << 3) * 528);
    const uint32_t bz = 0, br = 32 * 528, bc = 64 * 528;

    // epilogue ownership (kq == 0 warps only)
    const int r1 = lane >> 2;
    const int coll = (cg << 3) + ((lane & 3) << 1);
    const int hidg = (c << 5) + coll;
    const size_t brow1 = (size_t)(g * 16 + r1);
    const size_t brow2 = brow1 + 8;
    const int kt = hidg >> 4, kin = hidg & 15;
    const uint32_t po1 = (uint32_t)(kt * 768 + r1 * 48 + kin * 2);
    const uint32_t po2 = po1 + 8 * 48;

    float hp[4] = {0.f, 0.f, 0.f, 0.f};

    // wx for step 0 (epilogue warps)
    float2 wxv[3][2];
    if (kq == 0) {
        const float* p1 = wx + (brow1 * SEQ) * G3 + hidg;
        const float* p2 = wx + (brow2 * SEQ) * G3 + hidg;
        wxv[0][0] = *(const float2*)(p1);       wxv[0][1] = *(const float2*)(p2);
        wxv[1][0] = *(const float2*)(p1 + 256); wxv[1][1] = *(const float2*)(p2 + 256);
        wxv[2][0] = *(const float2*)(p1 + 512); wxv[2][1] = *(const float2*)(p2 + 512);
    }

    for (int t = 0; t < SEQ; ++t) {
        // ---- prefetch wx for step t+1 (hidden under this step's MMA) ----
        float2 wxn[3][2];
        if (kq == 0) {
            const int tn = (t + 1 < SEQ) ? t + 1 : t;
            const float* p1 = wx + (brow1 * SEQ + tn) * G3 + hidg;
            const float* p2 = wx + (brow2 * SEQ + tn) * G3 + hidg;
            wxn[0][0] = *(const float2*)(p1);       wxn[0][1] = *(const float2*)(p2);
            wxn[1][0] = *(const float2*)(p1 + 256); wxn[1][1] = *(const float2*)(p2 + 256);
            wxn[2][0] = *(const float2*)(p1 + 512); wxn[2][1] = *(const float2*)(p2 + 512);
        }

        // ---- MMA over this warp's 4 k-tiles ----
        float dz[4] = {0.f, 0.f, 0.f, 0.f};
        float dr[4] = {0.f, 0.f, 0.f, 0.f};
        float dc[4] = {0.f, 0.f, 0.f, 0.f};
#pragma unroll
        for (int i = 0; i < 4; ++i) {
            const int ktl = (kq << 2) + i;
            uint32_t ah[4], al[4];
            const uint32_t ab = sAu + (uint32_t)(ktl * 768) + aoff;
            LDSM4(ah, ab);
            LDSM4(al, ab + 12288);
            const uint32_t ko = bbase + (uint32_t)(ktl * 32);

            uint32_t bf[4];
            LDSM4(bf, ko + bz);                  // regs 0,1 = hi; 2,3 = lo
            MMA16816(dz, ah, bf);
            MMA16816(dz, al, bf);
            MMA16816(dz, ah, bf + 2);

            LDSM4(bf, ko + br);
            MMA16816(dr, ah, bf);
            MMA16816(dr, al, bf);
            MMA16816(dr, ah, bf + 2);

            LDSM4(bf, ko + bc);
            MMA16816(dc, ah, bf);
            MMA16816(dc, al, bf);
            MMA16816(dc, ah, bf + 2);
        }

        // ---- k reduction through smem (3 partial sources) ----
        if (kq) {
            float* s = red + (((kq - 1) * 4 + cg) * 32 + lane) * 12;
            *(float4*)(s + 0) = make_float4(dz[0], dz[1], dz[2], dz[3]);
            *(float4*)(s + 4) = make_float4(dr[0], dr[1], dr[2], dr[3]);
            *(float4*)(s + 8) = make_float4(dc[0], dc[1], dc[2], dc[3]);
        }
        __syncthreads();

        float hn[4];
        if (kq == 0) {
#pragma unroll
            for (int s3 = 0; s3 < 3; ++s3) {
                const float* s = red + ((s3 * 4 + cg) * 32 + lane) * 12;
                const float4 vz = *(const float4*)(s + 0);
                const float4 vr = *(const float4*)(s + 4);
                const float4 vc = *(const float4*)(s + 8);
                dz[0] += vz.x; dz[1] += vz.y; dz[2] += vz.z; dz[3] += vz.w;
                dr[0] += vr.x; dr[1] += vr.y; dr[2] += vr.z; dr[3] += vr.w;
                dc[0] += vc.x; dc[1] += vc.y; dc[2] += vc.z; dc[3] += vc.w;
            }

            // gates + h update
#pragma unroll
            for (int i = 0; i < 4; ++i) {
                const int rs = i >> 1;
                const float wzv = (i & 1) ? wxv[0][rs].y : wxv[0][rs].x;
                const float wrv = (i & 1) ? wxv[1][rs].y : wxv[1][rs].x;
                const float wcv = (i & 1) ? wxv[2][rs].y : wxv[2][rs].x;
                const float z  = sigmoidf_(wzv + dz[i]);
                const float rg = sigmoidf_(wrv + dr[i]);
                const float cc = tanhf_(wcv + rg * dc[i]);
                hn[i] = z * hp[i] + (1.f - z) * cc;
                hp[i] = hn[i];
            }

            // publish h_{t+1} bf16 hi/lo to the exchange buffer
            const int nb = (t + 1) & 1;
            char* ex = (char*)hx + (size_t)(nb * 16 + g) * A_BYTES;
            uint32_t hw[2], lw[2];
#pragma unroll
            for (int s2 = 0; s2 < 2; ++s2) {
                __nv_bfloat16 h0 = __float2bfloat16(hn[2*s2]);
                __nv_bfloat16 h1 = __float2bfloat16(hn[2*s2+1]);
                __nv_bfloat16 l0 = __float2bfloat16(hn[2*s2]   - __bfloat162float(h0));
                __nv_bfloat16 l1 = __float2bfloat16(hn[2*s2+1] - __bfloat162float(h1));
                hw[s2] = (uint32_t)__bfloat16_as_ushort(h0) |
                         ((uint32_t)__bfloat16_as_ushort(h1) << 16);
                lw[s2] = (uint32_t)__bfloat16_as_ushort(l0) |
                         ((uint32_t)__bfloat16_as_ushort(l1) << 16);
            }
            *(uint32_t*)(ex + po1)         = hw[0];
            *(uint32_t*)(ex + po2)         = hw[1];
            *(uint32_t*)(ex + 12288 + po1) = lw[0];
            *(uint32_t*)(ex + 12288 + po2) = lw[1];
        }

        // ---- cluster barrier ----
        asm volatile("barrier.cluster.arrive.aligned;" ::: "memory");

        // out_x / hT stores off the critical path
        if (kq == 0) {
            float* o1 = out_x + (brow1 * SEQ + t) * HID + hidg;
            float* o2 = out_x + (brow2 * SEQ + t) * HID + hidg;
            *(float2*)o1 = make_float2(hn[0], hn[1]);
            *(float2*)o2 = make_float2(hn[2], hn[3]);
            if (t == SEQ - 1) {
                *(float2*)(hT_out + brow1 * 512 + hidg) = make_float2(hn[0], hn[1]);
                *(float2*)(hT_out + brow2 * 512 + hidg) = make_float2(hn[2], hn[3]);
            }
            // rotate wx pipeline registers
#pragma unroll
            for (int a3 = 0; a3 < 3; ++a3) {
                wxv[a3][0] = wxn[a3][0];
                wxv[a3][1] = wxn[a3][1];
            }
        }

        asm volatile("barrier.cluster.wait.aligned;" ::: "memory");

        // ---- reload full A image (linear 24KB copy, 512 threads) ----
        {
            const int nb = (t + 1) & 1;
            const uint4* src = (const uint4*)((const char*)hx +
                                              (size_t)(nb * 16 + g) * A_BYTES);
            uint4* dst = (uint4*)sA;
#pragma unroll
            for (int i = 0; i < 3; ++i)
                dst[tid + 512 * i] = src[tid + 512 * i];
        }
        __syncthreads();
    }
}

// ---------------------------------------------------------------------------
// Launch
// ---------------------------------------------------------------------------
extern "C" void kernel_launch(void* const* d_in, const int* in_sizes, int n_in,
                              void* d_out, int out_size)
{
    const float* x   = (const float*)d_in[0];
    const float* Wd  = (const float*)d_in[1];
    const float* Wdg = (const float*)d_in[2];
    const float* Wo  = (const float*)d_in[3];
    const float* Wog = (const float*)d_in[4];
    const float* Ud  = (const float*)d_in[5];
    const float* Udg = (const float*)d_in[6];
    const float* Uo  = (const float*)d_in[7];
    const float* Uog = (const float*)d_in[8];
    const float* bb  = (const float*)d_in[9];
    float* out = (float*)d_out;

    float *pT, *pWX, *pX1, *pP, *pQ, *pPu, *pQu, *pUeff;
    __nv_bfloat16 *pUhi, *pUlo, *pHX;
    cudaGetSymbolAddress((void**)&pT,    g_t_buf);
    cudaGetSymbolAddress((void**)&pWX,   g_wx_buf);
    cudaGetSymbolAddress((void**)&pX1,   g_x1);
    cudaGetSymbolAddress((void**)&pP,    g_P);
    cudaGetSymbolAddress((void**)&pQ,    g_Q);
    cudaGetSymbolAddress((void**)&pPu,   g_Pu);
    cudaGetSymbolAddress((void**)&pQu,   g_Qu);
    cudaGetSymbolAddress((void**)&pUeff, g_Ueff);
    cudaGetSymbolAddress((void**)&pUhi,  g_Uhi);
    cudaGetSymbolAddress((void**)&pUlo,  g_Ulo);
    cudaGetSymbolAddress((void**)&pHX,   g_hx);

    cudaFuncSetAttribute(rnn_hmma, cudaFuncAttributeMaxDynamicSharedMemorySize,
                         RNN_SMEM);

    pack_kernel<<<(LAYERS * RANKSUM * G3 + 255) / 256, 256>>>(Wd, Wdg, Wo, Wog,
                                                              Ud, Udg, Uo, Uog);
    for (int l = 0; l < LAYERS; ++l)
        gemm_tiled<<<dim3(HID / 64, G3 / 64), 256>>>(
            pPu + (size_t)l * HID * RANKSUM, pQu + (size_t)l * RANKSUM * G3,
            nullptr, pUeff + (size_t)l * HID * G3, HID, G3, RANKSUM);
    split_u<<<(LAYERS * 8 * 96 * 256 + 255) / 256, 256>>>();

    const size_t OUT0 = (size_t)ROWS * HID;

    for (int l = 0; l < LAYERS; ++l) {
        const float* xin = (l == 0) ? x : pX1;
        gemm_tiled<<<dim3(ROWS / 64, 2), 256>>>(
            xin, pP + (size_t)l * NIN * RANKSUM, nullptr, pT, ROWS, RANKSUM, NIN);
        gemm_tiled<<<dim3(ROWS / 64, G3 / 64), 256>>>(
            pT, pQ + (size_t)l * RANKSUM * G3, bb + l * G3, pWX, ROWS, G3, RANKSUM);
        float* ox = (l == LAYERS - 1) ? out : pX1;
        rnn_hmma<<<128, 512, RNN_SMEM>>>(
            pUhi + (size_t)l * 8 * BTILE, pUlo + (size_t)l * 8 * BTILE,
            pWX, ox, out + OUT0 + l * HID, pHX);
    }
}

// round 9
// speedup vs baseline: 1.7771x; 1.1019x over previous
#include <cuda_runtime.h>
#include <cuda_bf16.h>
#include <cstdint>
#include <cstddef>

// ---------------------------------------------------------------------------
// Problem constants
// ---------------------------------------------------------------------------
#define BATCH   256
#define SEQ     512
#define NIN     256
#define HID     256
#define G3      768
#define LAYERS  2
#define ROWS    (BATCH*SEQ)
#define RANKSUM 96

// ---------------------------------------------------------------------------
// Static device scratch (no cudaMalloc allowed)
// ---------------------------------------------------------------------------
__device__ float g_wx_buf[(size_t)ROWS * G3];
__device__ float g_x1[(size_t)ROWS * HID];
__device__ float g_P [LAYERS * NIN * RANKSUM];
__device__ float g_Q [LAYERS * RANKSUM * G3];
__device__ float g_Pu[LAYERS * HID * RANKSUM];
__device__ float g_Qu[LAYERS * RANKSUM * G3];
__device__ float g_Ueff[LAYERS * HID * G3];

// stage-1 output as bf16 hi/lo: [row][hi 96 | lo 96]  (384 B/row)
__device__ __nv_bfloat16 g_t16[(size_t)ROWS * 192];
// Q as bf16 hi/lo: [layer][n 768][hi 96 | lo 96]
__device__ __nv_bfloat16 g_q16[(size_t)LAYERS * G3 * 192];

// U as bf16 hi/lo in B-operand layout: per (layer, cta): [96 n][264 k-padded]
#define BPAD  264                         // 528 bytes per row (bank step 4)
#define BTILE (96 * BPAD)                 // elems per (l, c) per precision
__device__ __nv_bfloat16 g_Uhi[(size_t)LAYERS * 8 * BTILE];
__device__ __nv_bfloat16 g_Ulo[(size_t)LAYERS * 8 * BTILE];

// h exchange: A-tile images [buf 2][group 16][hi 12288B | lo 12288B]
__device__ __nv_bfloat16 g_hx[2 * 16 * 2 * 6144];

// ---------------------------------------------------------------------------
// PTX helpers (baseline-target-safe: ldmatrix + mma.sync only)
// ---------------------------------------------------------------------------
__device__ __forceinline__ uint32_t smem_u32(const void* p)
{
    uint32_t a;
    asm("{ .reg .u64 t; cvta.to.shared.u64 t, %1; cvt.u32.u64 %0, t; }"
        : "=r"(a) : "l"(p));
    return a;
}

#define LDSM4(R, addr) \
    asm volatile("ldmatrix.sync.aligned.m8n8.x4.shared.b16 {%0,%1,%2,%3}, [%4];" \
        : "=r"((R)[0]), "=r"((R)[1]), "=r"((R)[2]), "=r"((R)[3]) : "r"(addr))
#define MMA16816(D, A, B) \
    asm volatile("mma.sync.aligned.m16n8k16.row.col.f32.bf16.bf16.f32 " \
        "{%0,%1,%2,%3}, {%4,%5,%6,%7}, {%8,%9}, {%0,%1,%2,%3};" \
        : "+f"((D)[0]), "+f"((D)[1]), "+f"((D)[2]), "+f"((D)[3]) \
        : "r"((A)[0]), "r"((A)[1]), "r"((A)[2]), "r"((A)[3]), \
          "r"((B)[0]), "r"((B)[1]))

// ---------------------------------------------------------------------------
// Pack kernel: concatenate low-rank factors
// ---------------------------------------------------------------------------
__global__ void pack_kernel(const float* __restrict__ Wd, const float* __restrict__ Wdg,
                            const float* __restrict__ Wo, const float* __restrict__ Wog,
                            const float* __restrict__ Ud, const float* __restrict__ Udg,
                            const float* __restrict__ Uo, const float* __restrict__ Uog)
{
    int idx = blockIdx.x * 256 + threadIdx.x;
    const int QN = LAYERS * RANKSUM * G3;
    const int PN = LAYERS * NIN * RANKSUM;
    if (idx < QN) {
        int l = idx / (RANKSUM * G3);
        int rem = idx - l * (RANKSUM * G3);
        int r = rem / G3, n = rem - r * G3;
        g_Q[idx]  = (r < 64) ? Wdg[(l*64 + r) * G3 + n] : Wog[(l*32 + (r-64)) * G3 + n];
        g_Qu[idx] = (r < 64) ? Udg[(l*64 + r) * G3 + n] : Uog[(l*32 + (r-64)) * G3 + n];
    }
    if (idx < PN) {
        int l = idx / (NIN * RANKSUM);
        int rem = idx - l * (NIN * RANKSUM);
        int k = rem / RANKSUM, j = rem - k * RANKSUM;
        g_P[idx]  = (j < 64) ? Wd[(l*NIN + k) * 64 + j] : Wo[(l*NIN + k) * 32 + (j-64)];
        g_Pu[idx] = (j < 64) ? Ud[(l*NIN + k) * 64 + j] : Uo[(l*NIN + k) * 32 + (j-64)];
    }
}

// ---------------------------------------------------------------------------
// Split Ueff (B-operand layout) and Q (wx2 B layout) into bf16 hi/lo.
// ---------------------------------------------------------------------------
__global__ void split_uq()
{
    int idx = blockIdx.x * 256 + threadIdx.x;
    const int UN = LAYERS * 8 * 96 * 256;      // 393216
    const int QN = LAYERS * G3 * 96;           // 147456
    if (idx < UN) {
        int k = idx & 255;
        int n = (idx >> 8) % 96;
        int c = (idx >> 8) / 96 % 8;
        int l = idx / (8 * 96 * 256);
        int gatecol = ((n >> 5) << 8) + (c << 5) + (n & 31);
        float v = g_Ueff[(size_t)l * HID * G3 + (size_t)k * G3 + gatecol];
        __nv_bfloat16 hi = __float2bfloat16(v);
        __nv_bfloat16 lo = __float2bfloat16(v - __bfloat162float(hi));
        size_t o = ((size_t)l * 8 + c) * BTILE + n * BPAD + k;
        g_Uhi[o] = hi;
        g_Ulo[o] = lo;
    }
    if (idx < QN) {
        int k = idx % 96;
        int n = (idx / 96) % G3;
        int l = idx / (96 * G3);
        float v = g_Q[((size_t)l * RANKSUM + k) * G3 + n];
        __nv_bfloat16 hi = __float2bfloat16(v);
        __nv_bfloat16 lo = __float2bfloat16(v - __bfloat162float(hi));
        size_t o = ((size_t)l * G3 + n) * 192 + k;
        g_q16[o]      = hi;
        g_q16[o + 96] = lo;
    }
}

// ---------------------------------------------------------------------------
// Generic tiled fp32 GEMM: C[M,N] = A[M,K] @ B[K,N]   (used for Ueff only)
// ---------------------------------------------------------------------------
__global__ void __launch_bounds__(256)
gemm_tiled(const float* __restrict__ A, const float* __restrict__ B,
           float* __restrict__ C, int M, int N, int K)
{
    __shared__ float As[16][64];
    __shared__ float Bs[16][68];

    const int tid = threadIdx.x;
    const int tm = tid >> 4, tn = tid & 15;
    const size_t bm = (size_t)blockIdx.x * 64;
    const int bn = blockIdx.y * 64;

    const int ar = tid >> 2, ak = (tid & 3) << 2;
    const int brow = tid >> 4, bcol = (tid & 15) << 2;

    float acc[4][4];
#pragma unroll
    for (int i = 0; i < 4; ++i)
#pragma unroll
        for (int j = 0; j < 4; ++j) acc[i][j] = 0.f;

    for (int k0 = 0; k0 < K; k0 += 16) {
        float4 av = *(const float4*)(A + (bm + ar) * (size_t)K + k0 + ak);
        As[ak + 0][ar] = av.x; As[ak + 1][ar] = av.y;
        As[ak + 2][ar] = av.z; As[ak + 3][ar] = av.w;

        float4 bv = make_float4(0.f, 0.f, 0.f, 0.f);
        if (bn + bcol < N)
            bv = *(const float4*)(B + (size_t)(k0 + brow) * N + bn + bcol);
        *(float4*)&Bs[brow][bcol] = bv;
        __syncthreads();

#pragma unroll
        for (int k = 0; k < 16; ++k) {
            float4 a = *(const float4*)&As[k][tm << 2];
            float4 b = *(const float4*)&Bs[k][tn << 2];
            acc[0][0] = fmaf(a.x, b.x, acc[0][0]); acc[0][1] = fmaf(a.x, b.y, acc[0][1]);
            acc[0][2] = fmaf(a.x, b.z, acc[0][2]); acc[0][3] = fmaf(a.x, b.w, acc[0][3]);
            acc[1][0] = fmaf(a.y, b.x, acc[1][0]); acc[1][1] = fmaf(a.y, b.y, acc[1][1]);
            acc[1][2] = fmaf(a.y, b.z, acc[1][2]); acc[1][3] = fmaf(a.y, b.w, acc[1][3]);
            acc[2][0] = fmaf(a.z, b.x, acc[2][0]); acc[2][1] = fmaf(a.z, b.y, acc[2][1]);
            acc[2][2] = fmaf(a.z, b.z, acc[2][2]); acc[2][3] = fmaf(a.z, b.w, acc[2][3]);
            acc[3][0] = fmaf(a.w, b.x, acc[3][0]); acc[3][1] = fmaf(a.w, b.y, acc[3][1]);
            acc[3][2] = fmaf(a.w, b.z, acc[3][2]); acc[3][3] = fmaf(a.w, b.w, acc[3][3]);
        }
        __syncthreads();
    }

#pragma unroll
    for (int i = 0; i < 4; ++i) {
        size_t row = bm + (tm << 2) + i;
#pragma unroll
        for (int j = 0; j < 4; ++j) {
            int colj = bn + (tn << 2) + j;
            if (colj < N)
                C[row * (size_t)N + colj] = acc[i][j];
        }
    }
}

// ---------------------------------------------------------------------------
// Stage-1 GEMM with bf16 hi/lo output: T16 = x @ P  (M=131072, N=96, K=256)
// Same tiling as gemm_tiled; epilogue splits each value into hi/lo bf16.
// ---------------------------------------------------------------------------
__global__ void __launch_bounds__(256)
gemm_s1(const float* __restrict__ A, const float* __restrict__ B,
        __nv_bfloat16* __restrict__ T16, int K)
{
    __shared__ float As[16][64];
    __shared__ float Bs[16][68];

    const int tid = threadIdx.x;
    const int tm = tid >> 4, tn = tid & 15;
    const size_t bm = (size_t)blockIdx.x * 64;
    const int bn = blockIdx.y * 64;

    const int ar = tid >> 2, ak = (tid & 3) << 2;
    const int brow = tid >> 4, bcol = (tid & 15) << 2;

    float acc[4][4];
#pragma unroll
    for (int i = 0; i < 4; ++i)
#pragma unroll
        for (int j = 0; j < 4; ++j) acc[i][j] = 0.f;

    for (int k0 = 0; k0 < K; k0 += 16) {
        float4 av = *(const float4*)(A + (bm + ar) * (size_t)K + k0 + ak);
        As[ak + 0][ar] = av.x; As[ak + 1][ar] = av.y;
        As[ak + 2][ar] = av.z; As[ak + 3][ar] = av.w;

        float4 bv = make_float4(0.f, 0.f, 0.f, 0.f);
        if (bn + bcol < RANKSUM)
            bv = *(const float4*)(B + (size_t)(k0 + brow) * RANKSUM + bn + bcol);
        *(float4*)&Bs[brow][bcol] = bv;
        __syncthreads();

#pragma unroll
        for (int k = 0; k < 16; ++k) {
            float4 a = *(const float4*)&As[k][tm << 2];
            float4 b = *(const float4*)&Bs[k][tn << 2];
            acc[0][0] = fmaf(a.x, b.x, acc[0][0]); acc[0][1] = fmaf(a.x, b.y, acc[0][1]);
            acc[0][2] = fmaf(a.x, b.z, acc[0][2]); acc[0][3] = fmaf(a.x, b.w, acc[0][3]);
            acc[1][0] = fmaf(a.y, b.x, acc[1][0]); acc[1][1] = fmaf(a.y, b.y, acc[1][1]);
            acc[1][2] = fmaf(a.y, b.z, acc[1][2]); acc[1][3] = fmaf(a.y, b.w, acc[1][3]);
            acc[2][0] = fmaf(a.z, b.x, acc[2][0]); acc[2][1] = fmaf(a.z, b.y, acc[2][1]);
            acc[2][2] = fmaf(a.z, b.z, acc[2][2]); acc[2][3] = fmaf(a.z, b.w, acc[2][3]);
            acc[3][0] = fmaf(a.w, b.x, acc[3][0]); acc[3][1] = fmaf(a.w, b.y, acc[3][1]);
            acc[3][2] = fmaf(a.w, b.z, acc[3][2]); acc[3][3] = fmaf(a.w, b.w, acc[3][3]);
        }
        __syncthreads();
    }

#pragma unroll
    for (int i = 0; i < 4; ++i) {
        size_t row = bm + (tm << 2) + i;
#pragma unroll
        for (int j = 0; j < 4; ++j) {
            int colj = bn + (tn << 2) + j;
            if (colj < RANKSUM) {
                float v = acc[i][j];
                __nv_bfloat16 hi = __float2bfloat16(v);
                __nv_bfloat16 lo = __float2bfloat16(v - __bfloat162float(hi));
                T16[row * 192 + colj]      = hi;
                T16[row * 192 + 96 + colj] = lo;
            }
        }
    }
}

// ---------------------------------------------------------------------------
// Stage-2 HMMA GEMM: wx[M,768] = T16[M,96] @ Q16^T + bias
// C tile 128x64, 256 threads = 8 warps (4m x 2n), warp tile 32x32.
// A/B hi/lo bf16, 3 accumulation passes. Grid (12 n-blocks, 1024 m-blocks) —
// n-fastest so the 12 CTAs sharing one T tile are co-resident (L2 reuse).
// SMEM rows padded to 416B: ldmatrix conflict-free.
// ---------------------------------------------------------------------------
#define WX2_A_BYTES (128 * 416)           // 53248
#define WX2_B_BYTES (64 * 416)            // 26624
#define WX2_SMEM    (WX2_A_BYTES + WX2_B_BYTES)

__global__ void __launch_bounds__(256)
wx2_hmma(const __nv_bfloat16* __restrict__ T16,
         const __nv_bfloat16* __restrict__ Q16,   // layer base
         const float* __restrict__ bias,          // layer base
         float* __restrict__ C)
{
    extern __shared__ char sm[];
    char* sA = sm;
    char* sB = sm + WX2_A_BYTES;

    const int tid = threadIdx.x;
    const int w = tid >> 5, lane = tid & 31;
    const int wm = w >> 1, wn = w & 1;
    const size_t bm = (size_t)blockIdx.y * 128;
    const int bn = blockIdx.x * 64;

    // ---- load A tile: 128 rows x 24 uint4 (hi|lo), pad row to 416B ----
    {
        const uint4* src = (const uint4*)T16 + bm * 24;
#pragma unroll
        for (int i = 0; i < 12; ++i) {
            int u = tid + 256 * i;
            int row = u / 24, ir = u - row * 24;
            uint32_t off = (uint32_t)(row * 416 + ir * 16 + ((ir >= 12) ? 16 : 0));
            *(uint4*)(sA + off) = src[u];
        }
        // B tile: 64 rows x 24 uint4
        const uint4* srcB = (const uint4*)Q16 + (size_t)bn * 24;
#pragma unroll
        for (int i = 0; i < 6; ++i) {
            int u = tid + 256 * i;
            int row = u / 24, ir = u - row * 24;
            uint32_t off = (uint32_t)(row * 416 + ir * 16 + ((ir >= 12) ? 16 : 0));
            *(uint4*)(sB + off) = srcB[u];
        }
    }
    __syncthreads();

    const uint32_t sAu = smem_u32(sA);
    const uint32_t sBu = smem_u32(sB);

    // A ldmatrix lane address (m16k16, one precision per LDSM4)
    const int rr = lane & 7;
    const uint32_t aoff = (uint32_t)((wm * 32 + ((lane >> 3) & 1) * 8 + rr) * 416
                                     + (lane >> 4) * 16);
    // B fused hi/lo ldmatrix (n8k16 hi + n8k16 lo per LDSM4)
    const int q = lane >> 3;
    const uint32_t boff = (uint32_t)((wn * 32 + rr) * 416 + (q & 1) * 16
                                     + (q >> 1) * 208);

    float acc[2][4][4];
#pragma unroll
    for (int mt = 0; mt < 2; ++mt)
#pragma unroll
        for (int nt = 0; nt < 4; ++nt)
#pragma unroll
            for (int i = 0; i < 4; ++i) acc[mt][nt][i] = 0.f;

#pragma unroll
    for (int kt = 0; kt < 6; ++kt) {
        uint32_t ahi[2][4], alo[2][4];
#pragma unroll
        for (int mt = 0; mt < 2; ++mt) {
            const uint32_t ab = sAu + aoff + (uint32_t)(mt * 16 * 416 + kt * 32);
            LDSM4(ahi[mt], ab);
            LDSM4(alo[mt], ab + 208);
        }
#pragma unroll
        for (int nt = 0; nt < 4; ++nt) {
            uint32_t bf[4];
            LDSM4(bf, sBu + boff + (uint32_t)(nt * 8 * 416 + kt * 32));
#pragma unroll
            for (int mt = 0; mt < 2; ++mt) {
                MMA16816(acc[mt][nt], ahi[mt], bf);      // hi*hi
                MMA16816(acc[mt][nt], alo[mt], bf);      // lo*hi
                MMA16816(acc[mt][nt], ahi[mt], bf + 2);  // hi*lo
            }
        }
    }

    // ---- epilogue: + bias, fp32 store ----
    const int er = lane >> 2;
    const int ec = (lane & 3) << 1;
#pragma unroll
    for (int nt = 0; nt < 4; ++nt) {
        const int col = bn + wn * 32 + nt * 8 + ec;
        const float b0 = bias[col], b1 = bias[col + 1];
#pragma unroll
        for (int mt = 0; mt < 2; ++mt) {
            const size_t r0 = bm + wm * 32 + mt * 16 + er;
            *(float2*)(C + r0 * G3 + col) =
                make_float2(acc[mt][nt][0] + b0, acc[mt][nt][1] + b1);
            *(float2*)(C + (r0 + 8) * G3 + col) =
                make_float2(acc[mt][nt][2] + b0, acc[mt][nt][3] + b1);
        }
    }
}

__device__ __forceinline__ float sigmoidf_(float x)
{
    return __fdividef(1.f, 1.f + __expf(-x));
}
__device__ __forceinline__ float tanhf_(float x)
{
    return __fdividef(2.f, 1.f + __expf(-2.f * x)) - 1.f;
}

// ---------------------------------------------------------------------------
// HMMA recurrent kernel (identical to R8 winner).
// ---------------------------------------------------------------------------
#define A_BYTES  24576
#define B_BYTES  (BTILE * 2)
#define RED_BYTES (3 * 4 * 32 * 12 * 4)
#define RNN_SMEM (A_BYTES + 2 * B_BYTES + RED_BYTES)

__global__ void __cluster_dims__(8, 1, 1) __launch_bounds__(512, 1)
rnn_hmma(const __nv_bfloat16* __restrict__ Uhi8,
         const __nv_bfloat16* __restrict__ Ulo8,
         const float* __restrict__ wx,
         float* __restrict__ out_x,
         float* __restrict__ hT_out,
         __nv_bfloat16* __restrict__ hx)
{
    extern __shared__ char sm[];
    char* sA  = sm;
    char* sBh = sm + A_BYTES;
    char* sBl = sBh + B_BYTES;
    float* red = (float*)(sBl + B_BYTES);

    const int c  = blockIdx.x & 7;
    const int g  = blockIdx.x >> 3;
    const int tid = threadIdx.x;
    const int w = tid >> 5, lane = tid & 31;
    const int kq = w >> 2;
    const int cg = w & 3;

    {
        const uint4* s0 = (const uint4*)(Uhi8 + (size_t)c * BTILE);
        const uint4* s1 = (const uint4*)(Ulo8 + (size_t)c * BTILE);
        uint4* d0 = (uint4*)sBh;
        uint4* d1 = (uint4*)sBl;
        for (int i = tid; i < B_BYTES / 16; i += 512) { d0[i] = s0[i]; d1[i] = s1[i]; }
        uint4 z4 = make_uint4(0u, 0u, 0u, 0u);
        uint4* a4 = (uint4*)sA;
        for (int i = tid; i < A_BYTES / 16; i += 512) a4[i] = z4;
    }
    __syncthreads();

    const uint32_t sAu  = smem_u32(sA);
    const uint32_t sBhu = smem_u32(sBh);
    const uint32_t sBlu = smem_u32(sBl);
    const int q = lane >> 3, rr = lane & 7;
    const uint32_t aoff = (uint32_t)(((q & 1) * 8 + rr) * 48 + (q >> 1) * 16);
    const uint32_t bbase = ((q < 2) ? sBhu : sBlu)
                         + (uint32_t)(rr * 528 + (q & 1) * 16)
                         + (uint32_t)((cg << 3) * 528);
    const uint32_t bz = 0, br = 32 * 528, bc = 64 * 528;

    const int r1 = lane >> 2;
    const int coll = (cg << 3) + ((lane & 3) << 1);
    const int hidg = (c << 5) + coll;
    const size_t brow1 = (size_t)(g * 16 + r1);
    const size_t brow2 = brow1 + 8;
    const int kt = hidg >> 4, kin = hidg & 15;
    const uint32_t po1 = (uint32_t)(kt * 768 + r1 * 48 + kin * 2);
    const uint32_t po2 = po1 + 8 * 48;

    float hp[4] = {0.f, 0.f, 0.f, 0.f};

    float2 wxv[3][2];
    if (kq == 0) {
        const float* p1 = wx + (brow1 * SEQ) * G3 + hidg;
        const float* p2 = wx + (brow2 * SEQ) * G3 + hidg;
        wxv[0][0] = *(const float2*)(p1);       wxv[0][1] = *(const float2*)(p2);
        wxv[1][0] = *(const float2*)(p1 + 256); wxv[1][1] = *(const float2*)(p2 + 256);
        wxv[2][0] = *(const float2*)(p1 + 512); wxv[2][1] = *(const float2*)(p2 + 512);
    }

    for (int t = 0; t < SEQ; ++t) {
        float2 wxn[3][2];
        if (kq == 0) {
            const int tn = (t + 1 < SEQ) ? t + 1 : t;
            const float* p1 = wx + (brow1 * SEQ + tn) * G3 + hidg;
            const float* p2 = wx + (brow2 * SEQ + tn) * G3 + hidg;
            wxn[0][0] = *(const float2*)(p1);       wxn[0][1] = *(const float2*)(p2);
            wxn[1][0] = *(const float2*)(p1 + 256); wxn[1][1] = *(const float2*)(p2 + 256);
            wxn[2][0] = *(const float2*)(p1 + 512); wxn[2][1] = *(const float2*)(p2 + 512);
        }

        float dz[4] = {0.f, 0.f, 0.f, 0.f};
        float dr[4] = {0.f, 0.f, 0.f, 0.f};
        float dc[4] = {0.f, 0.f, 0.f, 0.f};
#pragma unroll
        for (int i = 0; i < 4; ++i) {
            const int ktl = (kq << 2) + i;
            uint32_t ah[4], al[4];
            const uint32_t ab = sAu + (uint32_t)(ktl * 768) + aoff;
            LDSM4(ah, ab);
            LDSM4(al, ab + 12288);
            const uint32_t ko = bbase + (uint32_t)(ktl * 32);

            uint32_t bf[4];
            LDSM4(bf, ko + bz);
            MMA16816(dz, ah, bf);
            MMA16816(dz, al, bf);
            MMA16816(dz, ah, bf + 2);

            LDSM4(bf, ko + br);
            MMA16816(dr, ah, bf);
            MMA16816(dr, al, bf);
            MMA16816(dr, ah, bf + 2);

            LDSM4(bf, ko + bc);
            MMA16816(dc, ah, bf);
            MMA16816(dc, al, bf);
            MMA16816(dc, ah, bf + 2);
        }

        if (kq) {
            float* s = red + (((kq - 1) * 4 + cg) * 32 + lane) * 12;
            *(float4*)(s + 0) = make_float4(dz[0], dz[1], dz[2], dz[3]);
            *(float4*)(s + 4) = make_float4(dr[0], dr[1], dr[2], dr[3]);
            *(float4*)(s + 8) = make_float4(dc[0], dc[1], dc[2], dc[3]);
        }
        __syncthreads();

        float hn[4];
        if (kq == 0) {
#pragma unroll
            for (int s3 = 0; s3 < 3; ++s3) {
                const float* s = red + ((s3 * 4 + cg) * 32 + lane) * 12;
                const float4 vz = *(const float4*)(s + 0);
                const float4 vr = *(const float4*)(s + 4);
                const float4 vc = *(const float4*)(s + 8);
                dz[0] += vz.x; dz[1] += vz.y; dz[2] += vz.z; dz[3] += vz.w;
                dr[0] += vr.x; dr[1] += vr.y; dr[2] += vr.z; dr[3] += vr.w;
                dc[0] += vc.x; dc[1] += vc.y; dc[2] += vc.z; dc[3] += vc.w;
            }

#pragma unroll
            for (int i = 0; i < 4; ++i) {
                const int rs = i >> 1;
                const float wzv = (i & 1) ? wxv[0][rs].y : wxv[0][rs].x;
                const float wrv = (i & 1) ? wxv[1][rs].y : wxv[1][rs].x;
                const float wcv = (i & 1) ? wxv[2][rs].y : wxv[2][rs].x;
                const float z  = sigmoidf_(wzv + dz[i]);
                const float rg = sigmoidf_(wrv + dr[i]);
                const float cc = tanhf_(wcv + rg * dc[i]);
                hn[i] = z * hp[i] + (1.f - z) * cc;
                hp[i] = hn[i];
            }

            const int nb = (t + 1) & 1;
            char* ex = (char*)hx + (size_t)(nb * 16 + g) * A_BYTES;
            uint32_t hw[2], lw[2];
#pragma unroll
            for (int s2 = 0; s2 < 2; ++s2) {
                __nv_bfloat16 h0 = __float2bfloat16(hn[2*s2]);
                __nv_bfloat16 h1 = __float2bfloat16(hn[2*s2+1]);
                __nv_bfloat16 l0 = __float2bfloat16(hn[2*s2]   - __bfloat162float(h0));
                __nv_bfloat16 l1 = __float2bfloat16(hn[2*s2+1] - __bfloat162float(h1));
                hw[s2] = (uint32_t)__bfloat16_as_ushort(h0) |
                         ((uint32_t)__bfloat16_as_ushort(h1) << 16);
                lw[s2] = (uint32_t)__bfloat16_as_ushort(l0) |
                         ((uint32_t)__bfloat16_as_ushort(l1) << 16);
            }
            *(uint32_t*)(ex + po1)         = hw[0];
            *(uint32_t*)(ex + po2)         = hw[1];
            *(uint32_t*)(ex + 12288 + po1) = lw[0];
            *(uint32_t*)(ex + 12288 + po2) = lw[1];
        }

        asm volatile("barrier.cluster.arrive.aligned;" ::: "memory");

        if (kq == 0) {
            float* o1 = out_x + (brow1 * SEQ + t) * HID + hidg;
            float* o2 = out_x + (brow2 * SEQ + t) * HID + hidg;
            *(float2*)o1 = make_float2(hn[0], hn[1]);
            *(float2*)o2 = make_float2(hn[2], hn[3]);
            if (t == SEQ - 1) {
                *(float2*)(hT_out + brow1 * 512 + hidg) = make_float2(hn[0], hn[1]);
                *(float2*)(hT_out + brow2 * 512 + hidg) = make_float2(hn[2], hn[3]);
            }
#pragma unroll
            for (int a3 = 0; a3 < 3; ++a3) {
                wxv[a3][0] = wxn[a3][0];
                wxv[a3][1] = wxn[a3][1];
            }
        }

        asm volatile("barrier.cluster.wait.aligned;" ::: "memory");

        {
            const int nb = (t + 1) & 1;
            const uint4* src = (const uint4*)((const char*)hx +
                                              (size_t)(nb * 16 + g) * A_BYTES);
            uint4* dst = (uint4*)sA;
#pragma unroll
            for (int i = 0; i < 3; ++i)
                dst[tid + 512 * i] = src[tid + 512 * i];
        }
        __syncthreads();
    }
}

// ---------------------------------------------------------------------------
// Launch
// ---------------------------------------------------------------------------
extern "C" void kernel_launch(void* const* d_in, const int* in_sizes, int n_in,
                              void* d_out, int out_size)
{
    const float* x   = (const float*)d_in[0];
    const float* Wd  = (const float*)d_in[1];
    const float* Wdg = (const float*)d_in[2];
    const float* Wo  = (const float*)d_in[3];
    const float* Wog = (const float*)d_in[4];
    const float* Ud  = (const float*)d_in[5];
    const float* Udg = (const float*)d_in[6];
    const float* Uo  = (const float*)d_in[7];
    const float* Uog = (const float*)d_in[8];
    const float* bb  = (const float*)d_in[9];
    float* out = (float*)d_out;

    float *pWX, *pX1, *pP, *pQ, *pPu, *pQu, *pUeff;
    __nv_bfloat16 *pUhi, *pUlo, *pHX, *pT16, *pQ16;
    cudaGetSymbolAddress((void**)&pWX,   g_wx_buf);
    cudaGetSymbolAddress((void**)&pX1,   g_x1);
    cudaGetSymbolAddress((void**)&pP,    g_P);
    cudaGetSymbolAddress((void**)&pQ,    g_Q);
    cudaGetSymbolAddress((void**)&pPu,   g_Pu);
    cudaGetSymbolAddress((void**)&pQu,   g_Qu);
    cudaGetSymbolAddress((void**)&pUeff, g_Ueff);
    cudaGetSymbolAddress((void**)&pUhi,  g_Uhi);
    cudaGetSymbolAddress((void**)&pUlo,  g_Ulo);
    cudaGetSymbolAddress((void**)&pHX,   g_hx);
    cudaGetSymbolAddress((void**)&pT16,  g_t16);
    cudaGetSymbolAddress((void**)&pQ16,  g_q16);

    cudaFuncSetAttribute(rnn_hmma, cudaFuncAttributeMaxDynamicSharedMemorySize,
                         RNN_SMEM);
    cudaFuncSetAttribute(wx2_hmma, cudaFuncAttributeMaxDynamicSharedMemorySize,
                         WX2_SMEM);

    pack_kernel<<<(LAYERS * RANKSUM * G3 + 255) / 256, 256>>>(Wd, Wdg, Wo, Wog,
                                                              Ud, Udg, Uo, Uog);
    for (int l = 0; l < LAYERS; ++l)
        gemm_tiled<<<dim3(HID / 64, G3 / 64), 256>>>(
            pPu + (size_t)l * HID * RANKSUM, pQu + (size_t)l * RANKSUM * G3,
            pUeff + (size_t)l * HID * G3, HID, G3, RANKSUM);
    split_uq<<<(LAYERS * 8 * 96 * 256 + 255) / 256, 256>>>();

    const size_t OUT0 = (size_t)ROWS * HID;

    for (int l = 0; l < LAYERS; ++l) {
        const float* xin = (l == 0) ? x : pX1;
        // stage-1: T16(hi/lo bf16) = x @ P
        gemm_s1<<<dim3(ROWS / 64, 2), 256>>>(
            xin, pP + (size_t)l * NIN * RANKSUM, pT16, NIN);
        // stage-2: wx = T16 @ Q16^T + b  (HMMA)
        wx2_hmma<<<dim3(G3 / 64, ROWS / 128), 256, WX2_SMEM>>>(
            pT16, pQ16 + (size_t)l * G3 * 192, bb + l * G3, pWX);
        // recurrence
        float* ox = (l == LAYERS - 1) ? out : pX1;
        rnn_hmma<<<128, 512, RNN_SMEM>>>(
            pUhi + (size_t)l * 8 * BTILE, pUlo + (size_t)l * 8 * BTILE,
            pWX, ox, out + OUT0 + l * HID, pHX);
    }
}

// round 10
// speedup vs baseline: 1.8840x; 1.0602x over previous
#include <cuda_runtime.h>
#include <cuda_bf16.h>
#include <cstdint>
#include <cstddef>

// ---------------------------------------------------------------------------
// Problem constants
// ---------------------------------------------------------------------------
#define BATCH   256
#define SEQ     512
#define NIN     256
#define HID     256
#define G3      768
#define LAYERS  2
#define ROWS    (BATCH*SEQ)
#define RANKSUM 96

// ---------------------------------------------------------------------------
// Static device scratch (no cudaMalloc allowed)
// ---------------------------------------------------------------------------
__device__ float g_wx_buf[(size_t)ROWS * G3];
__device__ float g_x1[(size_t)ROWS * HID];
__device__ float g_P [LAYERS * NIN * RANKSUM];
__device__ float g_Q [LAYERS * RANKSUM * G3];
__device__ float g_Pu[LAYERS * HID * RANKSUM];
__device__ float g_Qu[LAYERS * RANKSUM * G3];
__device__ float g_Ueff[LAYERS * HID * G3];

// stage-1 output as bf16 hi/lo: [row][hi 96 | lo 96]  (384 B/row)
__device__ __nv_bfloat16 g_t16[(size_t)ROWS * 192];
// Q as bf16 hi/lo: [layer][n 768][hi 96 | lo 96]
__device__ __nv_bfloat16 g_q16[(size_t)LAYERS * G3 * 192];

// U as bf16 hi/lo in B-operand layout: per (layer, cta): [96 n][264 k-padded]
#define BPAD  264                         // 528 bytes per row (bank step 4)
#define BTILE (96 * BPAD)                 // elems per (l, c) per precision
__device__ __nv_bfloat16 g_Uhi[(size_t)LAYERS * 8 * BTILE];
__device__ __nv_bfloat16 g_Ulo[(size_t)LAYERS * 8 * BTILE];

// h exchange: A-tile images [buf 2][group 16][hi 12288B | lo 12288B]
__device__ __nv_bfloat16 g_hx[2 * 16 * 2 * 6144];

// ---------------------------------------------------------------------------
// PTX helpers (baseline-target-safe: ldmatrix + mma.sync only)
// ---------------------------------------------------------------------------
__device__ __forceinline__ uint32_t smem_u32(const void* p)
{
    uint32_t a;
    asm("{ .reg .u64 t; cvta.to.shared.u64 t, %1; cvt.u32.u64 %0, t; }"
        : "=r"(a) : "l"(p));
    return a;
}

#define LDSM4(R, addr) \
    asm volatile("ldmatrix.sync.aligned.m8n8.x4.shared.b16 {%0,%1,%2,%3}, [%4];" \
        : "=r"((R)[0]), "=r"((R)[1]), "=r"((R)[2]), "=r"((R)[3]) : "r"(addr))
#define MMA16816(D, A, B) \
    asm volatile("mma.sync.aligned.m16n8k16.row.col.f32.bf16.bf16.f32 " \
        "{%0,%1,%2,%3}, {%4,%5,%6,%7}, {%8,%9}, {%0,%1,%2,%3};" \
        : "+f"((D)[0]), "+f"((D)[1]), "+f"((D)[2]), "+f"((D)[3]) \
        : "r"((A)[0]), "r"((A)[1]), "r"((A)[2]), "r"((A)[3]), \
          "r"((B)[0]), "r"((B)[1]))

// ---------------------------------------------------------------------------
// Pack kernel: concatenate low-rank factors
// ---------------------------------------------------------------------------
__global__ void pack_kernel(const float* __restrict__ Wd, const float* __restrict__ Wdg,
                            const float* __restrict__ Wo, const float* __restrict__ Wog,
                            const float* __restrict__ Ud, const float* __restrict__ Udg,
                            const float* __restrict__ Uo, const float* __restrict__ Uog)
{
    int idx = blockIdx.x * 256 + threadIdx.x;
    const int QN = LAYERS * RANKSUM * G3;
    const int PN = LAYERS * NIN * RANKSUM;
    if (idx < QN) {
        int l = idx / (RANKSUM * G3);
        int rem = idx - l * (RANKSUM * G3);
        int r = rem / G3, n = rem - r * G3;
        g_Q[idx]  = (r < 64) ? Wdg[(l*64 + r) * G3 + n] : Wog[(l*32 + (r-64)) * G3 + n];
        g_Qu[idx] = (r < 64) ? Udg[(l*64 + r) * G3 + n] : Uog[(l*32 + (r-64)) * G3 + n];
    }
    if (idx < PN) {
        int l = idx / (NIN * RANKSUM);
        int rem = idx - l * (NIN * RANKSUM);
        int k = rem / RANKSUM, j = rem - k * RANKSUM;
        g_P[idx]  = (j < 64) ? Wd[(l*NIN + k) * 64 + j] : Wo[(l*NIN + k) * 32 + (j-64)];
        g_Pu[idx] = (j < 64) ? Ud[(l*NIN + k) * 64 + j] : Uo[(l*NIN + k) * 32 + (j-64)];
    }
}

// ---------------------------------------------------------------------------
// Split Ueff (B-operand layout) and Q (wx2 B layout) into bf16 hi/lo.
// ---------------------------------------------------------------------------
__global__ void split_uq()
{
    int idx = blockIdx.x * 256 + threadIdx.x;
    const int UN = LAYERS * 8 * 96 * 256;      // 393216
    const int QN = LAYERS * G3 * 96;           // 147456
    if (idx < UN) {
        int k = idx & 255;
        int n = (idx >> 8) % 96;
        int c = (idx >> 8) / 96 % 8;
        int l = idx / (8 * 96 * 256);
        int gatecol = ((n >> 5) << 8) + (c << 5) + (n & 31);
        float v = g_Ueff[(size_t)l * HID * G3 + (size_t)k * G3 + gatecol];
        __nv_bfloat16 hi = __float2bfloat16(v);
        __nv_bfloat16 lo = __float2bfloat16(v - __bfloat162float(hi));
        size_t o = ((size_t)l * 8 + c) * BTILE + n * BPAD + k;
        g_Uhi[o] = hi;
        g_Ulo[o] = lo;
    }
    if (idx < QN) {
        int k = idx % 96;
        int n = (idx / 96) % G3;
        int l = idx / (96 * G3);
        float v = g_Q[((size_t)l * RANKSUM + k) * G3 + n];
        __nv_bfloat16 hi = __float2bfloat16(v);
        __nv_bfloat16 lo = __float2bfloat16(v - __bfloat162float(hi));
        size_t o = ((size_t)l * G3 + n) * 192 + k;
        g_q16[o]      = hi;
        g_q16[o + 96] = lo;
    }
}

// ---------------------------------------------------------------------------
// Ueff GEMM, both layers in one launch (blockIdx.z = layer):
// Ueff[l] = Pu[l] @ Qu[l]   (256 x 768, K = 96)
// ---------------------------------------------------------------------------
__global__ void __launch_bounds__(256)
gemm_ueff(const float* __restrict__ Pu, const float* __restrict__ Qu,
          float* __restrict__ Ueff)
{
    __shared__ float As[16][64];
    __shared__ float Bs[16][68];

    const int l = blockIdx.z;
    const float* A = Pu + (size_t)l * HID * RANKSUM;
    const float* B = Qu + (size_t)l * RANKSUM * G3;
    float* C = Ueff + (size_t)l * HID * G3;

    const int tid = threadIdx.x;
    const int tm = tid >> 4, tn = tid & 15;
    const size_t bm = (size_t)blockIdx.x * 64;
    const int bn = blockIdx.y * 64;

    const int ar = tid >> 2, ak = (tid & 3) << 2;
    const int brow = tid >> 4, bcol = (tid & 15) << 2;

    float acc[4][4];
#pragma unroll
    for (int i = 0; i < 4; ++i)
#pragma unroll
        for (int j = 0; j < 4; ++j) acc[i][j] = 0.f;

    for (int k0 = 0; k0 < RANKSUM; k0 += 16) {
        float4 av = *(const float4*)(A + (bm + ar) * RANKSUM + k0 + ak);
        As[ak + 0][ar] = av.x; As[ak + 1][ar] = av.y;
        As[ak + 2][ar] = av.z; As[ak + 3][ar] = av.w;

        float4 bv = *(const float4*)(B + (size_t)(k0 + brow) * G3 + bn + bcol);
        *(float4*)&Bs[brow][bcol] = bv;
        __syncthreads();

#pragma unroll
        for (int k = 0; k < 16; ++k) {
            float4 a = *(const float4*)&As[k][tm << 2];
            float4 b = *(const float4*)&Bs[k][tn << 2];
            acc[0][0] = fmaf(a.x, b.x, acc[0][0]); acc[0][1] = fmaf(a.x, b.y, acc[0][1]);
            acc[0][2] = fmaf(a.x, b.z, acc[0][2]); acc[0][3] = fmaf(a.x, b.w, acc[0][3]);
            acc[1][0] = fmaf(a.y, b.x, acc[1][0]); acc[1][1] = fmaf(a.y, b.y, acc[1][1]);
            acc[1][2] = fmaf(a.y, b.z, acc[1][2]); acc[1][3] = fmaf(a.y, b.w, acc[1][3]);
            acc[2][0] = fmaf(a.z, b.x, acc[2][0]); acc[2][1] = fmaf(a.z, b.y, acc[2][1]);
            acc[2][2] = fmaf(a.z, b.z, acc[2][2]); acc[2][3] = fmaf(a.z, b.w, acc[2][3]);
            acc[3][0] = fmaf(a.w, b.x, acc[3][0]); acc[3][1] = fmaf(a.w, b.y, acc[3][1]);
            acc[3][2] = fmaf(a.w, b.z, acc[3][2]); acc[3][3] = fmaf(a.w, b.w, acc[3][3]);
        }
        __syncthreads();
    }

#pragma unroll
    for (int i = 0; i < 4; ++i) {
        size_t row = bm + (tm << 2) + i;
#pragma unroll
        for (int j = 0; j < 4; ++j)
            C[row * G3 + bn + (tn << 2) + j] = acc[i][j];
    }
}

// ---------------------------------------------------------------------------
// Stage-1 GEMM with bf16 hi/lo output: T16 = x @ P  (M=131072, N=96, K=256)
// ---------------------------------------------------------------------------
__global__ void __launch_bounds__(256)
gemm_s1(const float* __restrict__ A, const float* __restrict__ B,
        __nv_bfloat16* __restrict__ T16, int K)
{
    __shared__ float As[16][64];
    __shared__ float Bs[16][68];

    const int tid = threadIdx.x;
    const int tm = tid >> 4, tn = tid & 15;
    const size_t bm = (size_t)blockIdx.x * 64;
    const int bn = blockIdx.y * 64;

    const int ar = tid >> 2, ak = (tid & 3) << 2;
    const int brow = tid >> 4, bcol = (tid & 15) << 2;

    float acc[4][4];
#pragma unroll
    for (int i = 0; i < 4; ++i)
#pragma unroll
        for (int j = 0; j < 4; ++j) acc[i][j] = 0.f;

    for (int k0 = 0; k0 < K; k0 += 16) {
        float4 av = *(const float4*)(A + (bm + ar) * (size_t)K + k0 + ak);
        As[ak + 0][ar] = av.x; As[ak + 1][ar] = av.y;
        As[ak + 2][ar] = av.z; As[ak + 3][ar] = av.w;

        float4 bv = make_float4(0.f, 0.f, 0.f, 0.f);
        if (bn + bcol < RANKSUM)
            bv = *(const float4*)(B + (size_t)(k0 + brow) * RANKSUM + bn + bcol);
        *(float4*)&Bs[brow][bcol] = bv;
        __syncthreads();

#pragma unroll
        for (int k = 0; k < 16; ++k) {
            float4 a = *(const float4*)&As[k][tm << 2];
            float4 b = *(const float4*)&Bs[k][tn << 2];
            acc[0][0] = fmaf(a.x, b.x, acc[0][0]); acc[0][1] = fmaf(a.x, b.y, acc[0][1]);
            acc[0][2] = fmaf(a.x, b.z, acc[0][2]); acc[0][3] = fmaf(a.x, b.w, acc[0][3]);
            acc[1][0] = fmaf(a.y, b.x, acc[1][0]); acc[1][1] = fmaf(a.y, b.y, acc[1][1]);
            acc[1][2] = fmaf(a.y, b.z, acc[1][2]); acc[1][3] = fmaf(a.y, b.w, acc[1][3]);
            acc[2][0] = fmaf(a.z, b.x, acc[2][0]); acc[2][1] = fmaf(a.z, b.y, acc[2][1]);
            acc[2][2] = fmaf(a.z, b.z, acc[2][2]); acc[2][3] = fmaf(a.z, b.w, acc[2][3]);
            acc[3][0] = fmaf(a.w, b.x, acc[3][0]); acc[3][1] = fmaf(a.w, b.y, acc[3][1]);
            acc[3][2] = fmaf(a.w, b.z, acc[3][2]); acc[3][3] = fmaf(a.w, b.w, acc[3][3]);
        }
        __syncthreads();
    }

#pragma unroll
    for (int i = 0; i < 4; ++i) {
        size_t row = bm + (tm << 2) + i;
#pragma unroll
        for (int j = 0; j < 4; ++j) {
            int colj = bn + (tn << 2) + j;
            if (colj < RANKSUM) {
                float v = acc[i][j];
                __nv_bfloat16 hi = __float2bfloat16(v);
                __nv_bfloat16 lo = __float2bfloat16(v - __bfloat162float(hi));
                T16[row * 192 + colj]      = hi;
                T16[row * 192 + 96 + colj] = lo;
            }
        }
    }
}

// ---------------------------------------------------------------------------
// Stage-2 HMMA GEMM: wx[M,768] = T16[M,96] @ Q16^T + bias  (unchanged R9)
// ---------------------------------------------------------------------------
#define WX2_A_BYTES (128 * 416)
#define WX2_B_BYTES (64 * 416)
#define WX2_SMEM    (WX2_A_BYTES + WX2_B_BYTES)

__global__ void __launch_bounds__(256)
wx2_hmma(const __nv_bfloat16* __restrict__ T16,
         const __nv_bfloat16* __restrict__ Q16,
         const float* __restrict__ bias,
         float* __restrict__ C)
{
    extern __shared__ char sm[];
    char* sA = sm;
    char* sB = sm + WX2_A_BYTES;

    const int tid = threadIdx.x;
    const int w = tid >> 5, lane = tid & 31;
    const int wm = w >> 1, wn = w & 1;
    const size_t bm = (size_t)blockIdx.y * 128;
    const int bn = blockIdx.x * 64;

    {
        const uint4* src = (const uint4*)T16 + bm * 24;
#pragma unroll
        for (int i = 0; i < 12; ++i) {
            int u = tid + 256 * i;
            int row = u / 24, ir = u - row * 24;
            uint32_t off = (uint32_t)(row * 416 + ir * 16 + ((ir >= 12) ? 16 : 0));
            *(uint4*)(sA + off) = src[u];
        }
        const uint4* srcB = (const uint4*)Q16 + (size_t)bn * 24;
#pragma unroll
        for (int i = 0; i < 6; ++i) {
            int u = tid + 256 * i;
            int row = u / 24, ir = u - row * 24;
            uint32_t off = (uint32_t)(row * 416 + ir * 16 + ((ir >= 12) ? 16 : 0));
            *(uint4*)(sB + off) = srcB[u];
        }
    }
    __syncthreads();

    const uint32_t sAu = smem_u32(sA);
    const uint32_t sBu = smem_u32(sB);

    const int rr = lane & 7;
    const uint32_t aoff = (uint32_t)((wm * 32 + ((lane >> 3) & 1) * 8 + rr) * 416
                                     + (lane >> 4) * 16);
    const int q = lane >> 3;
    const uint32_t boff = (uint32_t)((wn * 32 + rr) * 416 + (q & 1) * 16
                                     + (q >> 1) * 208);

    float acc[2][4][4];
#pragma unroll
    for (int mt = 0; mt < 2; ++mt)
#pragma unroll
        for (int nt = 0; nt < 4; ++nt)
#pragma unroll
            for (int i = 0; i < 4; ++i) acc[mt][nt][i] = 0.f;

#pragma unroll
    for (int kt = 0; kt < 6; ++kt) {
        uint32_t ahi[2][4], alo[2][4];
#pragma unroll
        for (int mt = 0; mt < 2; ++mt) {
            const uint32_t ab = sAu + aoff + (uint32_t)(mt * 16 * 416 + kt * 32);
            LDSM4(ahi[mt], ab);
            LDSM4(alo[mt], ab + 208);
        }
#pragma unroll
        for (int nt = 0; nt < 4; ++nt) {
            uint32_t bf[4];
            LDSM4(bf, sBu + boff + (uint32_t)(nt * 8 * 416 + kt * 32));
#pragma unroll
            for (int mt = 0; mt < 2; ++mt) {
                MMA16816(acc[mt][nt], ahi[mt], bf);
                MMA16816(acc[mt][nt], alo[mt], bf);
                MMA16816(acc[mt][nt], ahi[mt], bf + 2);
            }
        }
    }

    const int er = lane >> 2;
    const int ec = (lane & 3) << 1;
#pragma unroll
    for (int nt = 0; nt < 4; ++nt) {
        const int col = bn + wn * 32 + nt * 8 + ec;
        const float b0 = bias[col], b1 = bias[col + 1];
#pragma unroll
        for (int mt = 0; mt < 2; ++mt) {
            const size_t r0 = bm + wm * 32 + mt * 16 + er;
            *(float2*)(C + r0 * G3 + col) =
                make_float2(acc[mt][nt][0] + b0, acc[mt][nt][1] + b1);
            *(float2*)(C + (r0 + 8) * G3 + col) =
                make_float2(acc[mt][nt][2] + b0, acc[mt][nt][3] + b1);
        }
    }
}

__device__ __forceinline__ float sigmoidf_(float x)
{
    return __fdividef(1.f, 1.f + __expf(-x));
}
__device__ __forceinline__ float tanhf_(float x)
{
    return __fdividef(2.f, 1.f + __expf(-2.f * x)) - 1.f;
}

// ---------------------------------------------------------------------------
// HMMA recurrent kernel v4: B fragments hoisted to registers.
// U is time-invariant: each warp loads its 12 B-fragment LDSM4s ONCE before
// the t-loop (48 regs). In-loop work per warp: 8 A LDSM4 + 36 MMA.
// Everything else identical to the R8/R9 winner.
// ---------------------------------------------------------------------------
#define A_BYTES  24576
#define B_BYTES  (BTILE * 2)
#define RED_BYTES (3 * 4 * 32 * 12 * 4)
#define RNN_SMEM (A_BYTES + 2 * B_BYTES + RED_BYTES)

__global__ void __cluster_dims__(8, 1, 1) __launch_bounds__(512, 1)
rnn_hmma(const __nv_bfloat16* __restrict__ Uhi8,
         const __nv_bfloat16* __restrict__ Ulo8,
         const float* __restrict__ wx,
         float* __restrict__ out_x,
         float* __restrict__ hT_out,
         __nv_bfloat16* __restrict__ hx)
{
    extern __shared__ char sm[];
    char* sA  = sm;
    char* sBh = sm + A_BYTES;
    char* sBl = sBh + B_BYTES;
    float* red = (float*)(sBl + B_BYTES);

    const int c  = blockIdx.x & 7;
    const int g  = blockIdx.x >> 3;
    const int tid = threadIdx.x;
    const int w = tid >> 5, lane = tid & 31;
    const int kq = w >> 2;
    const int cg = w & 3;

    {
        const uint4* s0 = (const uint4*)(Uhi8 + (size_t)c * BTILE);
        const uint4* s1 = (const uint4*)(Ulo8 + (size_t)c * BTILE);
        uint4* d0 = (uint4*)sBh;
        uint4* d1 = (uint4*)sBl;
        for (int i = tid; i < B_BYTES / 16; i += 512) { d0[i] = s0[i]; d1[i] = s1[i]; }
        uint4 z4 = make_uint4(0u, 0u, 0u, 0u);
        uint4* a4 = (uint4*)sA;
        for (int i = tid; i < A_BYTES / 16; i += 512) a4[i] = z4;
    }
    __syncthreads();

    const uint32_t sAu  = smem_u32(sA);
    const uint32_t sBhu = smem_u32(sBh);
    const uint32_t sBlu = smem_u32(sBl);
    const int q = lane >> 3, rr = lane & 7;
    const uint32_t aoff = (uint32_t)(((q & 1) * 8 + rr) * 48 + (q >> 1) * 16);
    const uint32_t bbase = ((q < 2) ? sBhu : sBlu)
                         + (uint32_t)(rr * 528 + (q & 1) * 16)
                         + (uint32_t)((cg << 3) * 528);
    const uint32_t bz = 0, br = 32 * 528, bc = 64 * 528;

    // ---- hoist B fragments (time-invariant) into registers ----
    uint32_t bZ[4][4], bR[4][4], bC[4][4];
#pragma unroll
    for (int i = 0; i < 4; ++i) {
        const uint32_t ko = bbase + (uint32_t)(((kq << 2) + i) * 32);
        LDSM4(bZ[i], ko + bz);
        LDSM4(bR[i], ko + br);
        LDSM4(bC[i], ko + bc);
    }

    const int r1 = lane >> 2;
    const int coll = (cg << 3) + ((lane & 3) << 1);
    const int hidg = (c << 5) + coll;
    const size_t brow1 = (size_t)(g * 16 + r1);
    const size_t brow2 = brow1 + 8;
    const int kt = hidg >> 4, kin = hidg & 15;
    const uint32_t po1 = (uint32_t)(kt * 768 + r1 * 48 + kin * 2);
    const uint32_t po2 = po1 + 8 * 48;

    float hp[4] = {0.f, 0.f, 0.f, 0.f};

    float2 wxv[3][2];
    if (kq == 0) {
        const float* p1 = wx + (brow1 * SEQ) * G3 + hidg;
        const float* p2 = wx + (brow2 * SEQ) * G3 + hidg;
        wxv[0][0] = *(const float2*)(p1);       wxv[0][1] = *(const float2*)(p2);
        wxv[1][0] = *(const float2*)(p1 + 256); wxv[1][1] = *(const float2*)(p2 + 256);
        wxv[2][0] = *(const float2*)(p1 + 512); wxv[2][1] = *(const float2*)(p2 + 512);
    }

    for (int t = 0; t < SEQ; ++t) {
        float2 wxn[3][2];
        if (kq == 0) {
            const int tn = (t + 1 < SEQ) ? t + 1 : t;
            const float* p1 = wx + (brow1 * SEQ + tn) * G3 + hidg;
            const float* p2 = wx + (brow2 * SEQ + tn) * G3 + hidg;
            wxn[0][0] = *(const float2*)(p1);       wxn[0][1] = *(const float2*)(p2);
            wxn[1][0] = *(const float2*)(p1 + 256); wxn[1][1] = *(const float2*)(p2 + 256);
            wxn[2][0] = *(const float2*)(p1 + 512); wxn[2][1] = *(const float2*)(p2 + 512);
        }

        float dz[4] = {0.f, 0.f, 0.f, 0.f};
        float dr[4] = {0.f, 0.f, 0.f, 0.f};
        float dc[4] = {0.f, 0.f, 0.f, 0.f};
#pragma unroll
        for (int i = 0; i < 4; ++i) {
            const int ktl = (kq << 2) + i;
            uint32_t ah[4], al[4];
            const uint32_t ab = sAu + (uint32_t)(ktl * 768) + aoff;
            LDSM4(ah, ab);
            LDSM4(al, ab + 12288);

            MMA16816(dz, ah, bZ[i]);
            MMA16816(dz, al, bZ[i]);
            MMA16816(dz, ah, bZ[i] + 2);

            MMA16816(dr, ah, bR[i]);
            MMA16816(dr, al, bR[i]);
            MMA16816(dr, ah, bR[i] + 2);

            MMA16816(dc, ah, bC[i]);
            MMA16816(dc, al, bC[i]);
            MMA16816(dc, ah, bC[i] + 2);
        }

        if (kq) {
            float* s = red + (((kq - 1) * 4 + cg) * 32 + lane) * 12;
            *(float4*)(s + 0) = make_float4(dz[0], dz[1], dz[2], dz[3]);
            *(float4*)(s + 4) = make_float4(dr[0], dr[1], dr[2], dr[3]);
            *(float4*)(s + 8) = make_float4(dc[0], dc[1], dc[2], dc[3]);
        }
        __syncthreads();

        float hn[4];
        if (kq == 0) {
#pragma unroll
            for (int s3 = 0; s3 < 3; ++s3) {
                const float* s = red + ((s3 * 4 + cg) * 32 + lane) * 12;
                const float4 vz = *(const float4*)(s + 0);
                const float4 vr = *(const float4*)(s + 4);
                const float4 vc = *(const float4*)(s + 8);
                dz[0] += vz.x; dz[1] += vz.y; dz[2] += vz.z; dz[3] += vz.w;
                dr[0] += vr.x; dr[1] += vr.y; dr[2] += vr.z; dr[3] += vr.w;
                dc[0] += vc.x; dc[1] += vc.y; dc[2] += vc.z; dc[3] += vc.w;
            }

#pragma unroll
            for (int i = 0; i < 4; ++i) {
                const int rs = i >> 1;
                const float wzv = (i & 1) ? wxv[0][rs].y : wxv[0][rs].x;
                const float wrv = (i & 1) ? wxv[1][rs].y : wxv[1][rs].x;
                const float wcv = (i & 1) ? wxv[2][rs].y : wxv[2][rs].x;
                const float z  = sigmoidf_(wzv + dz[i]);
                const float rg = sigmoidf_(wrv + dr[i]);
                const float cc = tanhf_(wcv + rg * dc[i]);
                hn[i] = z * hp[i] + (1.f - z) * cc;
                hp[i] = hn[i];
            }

            const int nb = (t + 1) & 1;
            char* ex = (char*)hx + (size_t)(nb * 16 + g) * A_BYTES;
            uint32_t hw[2], lw[2];
#pragma unroll
            for (int s2 = 0; s2 < 2; ++s2) {
                __nv_bfloat16 h0 = __float2bfloat16(hn[2*s2]);
                __nv_bfloat16 h1 = __float2bfloat16(hn[2*s2+1]);
                __nv_bfloat16 l0 = __float2bfloat16(hn[2*s2]   - __bfloat162float(h0));
                __nv_bfloat16 l1 = __float2bfloat16(hn[2*s2+1] - __bfloat162float(h1));
                hw[s2] = (uint32_t)__bfloat16_as_ushort(h0) |
                         ((uint32_t)__bfloat16_as_ushort(h1) << 16);
                lw[s2] = (uint32_t)__bfloat16_as_ushort(l0) |
                         ((uint32_t)__bfloat16_as_ushort(l1) << 16);
            }
            *(uint32_t*)(ex + po1)         = hw[0];
            *(uint32_t*)(ex + po2)         = hw[1];
            *(uint32_t*)(ex + 12288 + po1) = lw[0];
            *(uint32_t*)(ex + 12288 + po2) = lw[1];
        }

        asm volatile("barrier.cluster.arrive.aligned;" ::: "memory");

        if (kq == 0) {
            float* o1 = out_x + (brow1 * SEQ + t) * HID + hidg;
            float* o2 = out_x + (brow2 * SEQ + t) * HID + hidg;
            *(float2*)o1 = make_float2(hn[0], hn[1]);
            *(float2*)o2 = make_float2(hn[2], hn[3]);
            if (t == SEQ - 1) {
                *(float2*)(hT_out + brow1 * 512 + hidg) = make_float2(hn[0], hn[1]);
                *(float2*)(hT_out + brow2 * 512 + hidg) = make_float2(hn[2], hn[3]);
            }
#pragma unroll
            for (int a3 = 0; a3 < 3; ++a3) {
                wxv[a3][0] = wxn[a3][0];
                wxv[a3][1] = wxn[a3][1];
            }
        }

        asm volatile("barrier.cluster.wait.aligned;" ::: "memory");

        {
            const int nb = (t + 1) & 1;
            const uint4* src = (const uint4*)((const char*)hx +
                                              (size_t)(nb * 16 + g) * A_BYTES);
            uint4* dst = (uint4*)sA;
#pragma unroll
            for (int i = 0; i < 3; ++i)
                dst[tid + 512 * i] = src[tid + 512 * i];
        }
        __syncthreads();
    }
}

// ---------------------------------------------------------------------------
// Launch
// ---------------------------------------------------------------------------
extern "C" void kernel_launch(void* const* d_in, const int* in_sizes, int n_in,
                              void* d_out, int out_size)
{
    const float* x   = (const float*)d_in[0];
    const float* Wd  = (const float*)d_in[1];
    const float* Wdg = (const float*)d_in[2];
    const float* Wo  = (const float*)d_in[3];
    const float* Wog = (const float*)d_in[4];
    const float* Ud  = (const float*)d_in[5];
    const float* Udg = (const float*)d_in[6];
    const float* Uo  = (const float*)d_in[7];
    const float* Uog = (const float*)d_in[8];
    const float* bb  = (const float*)d_in[9];
    float* out = (float*)d_out;

    float *pWX, *pX1, *pP, *pQ, *pPu, *pQu, *pUeff;
    __nv_bfloat16 *pUhi, *pUlo, *pHX, *pT16, *pQ16;
    cudaGetSymbolAddress((void**)&pWX,   g_wx_buf);
    cudaGetSymbolAddress((void**)&pX1,   g_x1);
    cudaGetSymbolAddress((void**)&pP,    g_P);
    cudaGetSymbolAddress((void**)&pQ,    g_Q);
    cudaGetSymbolAddress((void**)&pPu,   g_Pu);
    cudaGetSymbolAddress((void**)&pQu,   g_Qu);
    cudaGetSymbolAddress((void**)&pUeff, g_Ueff);
    cudaGetSymbolAddress((void**)&pUhi,  g_Uhi);
    cudaGetSymbolAddress((void**)&pUlo,  g_Ulo);
    cudaGetSymbolAddress((void**)&pHX,   g_hx);
    cudaGetSymbolAddress((void**)&pT16,  g_t16);
    cudaGetSymbolAddress((void**)&pQ16,  g_q16);

    cudaFuncSetAttribute(rnn_hmma, cudaFuncAttributeMaxDynamicSharedMemorySize,
                         RNN_SMEM);
    cudaFuncSetAttribute(wx2_hmma, cudaFuncAttributeMaxDynamicSharedMemorySize,
                         WX2_SMEM);

    // #1 pack, #2 gemm_ueff (both layers), #3 split -> rnn is launch #6 (ncu)
    pack_kernel<<<(LAYERS * RANKSUM * G3 + 255) / 256, 256>>>(Wd, Wdg, Wo, Wog,
                                                              Ud, Udg, Uo, Uog);
    gemm_ueff<<<dim3(HID / 64, G3 / 64, LAYERS), 256>>>(pPu, pQu, pUeff);
    split_uq<<<(LAYERS * 8 * 96 * 256 + 255) / 256, 256>>>();

    const size_t OUT0 = (size_t)ROWS * HID;

    for (int l = 0; l < LAYERS; ++l) {
        const float* xin = (l == 0) ? x : pX1;
        gemm_s1<<<dim3(ROWS / 64, 2), 256>>>(
            xin, pP + (size_t)l * NIN * RANKSUM, pT16, NIN);
        wx2_hmma<<<dim3(G3 / 64, ROWS / 128), 256, WX2_SMEM>>>(
            pT16, pQ16 + (size_t)l * G3 * 192, bb + l * G3, pWX);
        float* ox = (l == LAYERS - 1) ? out : pX1;
        rnn_hmma<<<128, 512, RNN_SMEM>>>(
            pUhi + (size_t)l * 8 * BTILE, pUlo + (size_t)l * 8 * BTILE,
            pWX, ox, out + OUT0 + l * HID, pHX);
    }
}

// round 11
// speedup vs baseline: 2.0006x; 1.0619x over previous
#include <cuda_runtime.h>
#include <cuda_bf16.h>
#include <cstdint>
#include <cstddef>

// ---------------------------------------------------------------------------
// Problem constants
// ---------------------------------------------------------------------------
#define BATCH   256
#define SEQ     512
#define NIN     256
#define HID     256
#define G3      768
#define LAYERS  2
#define ROWS    (BATCH*SEQ)
#define RANKSUM 96

// ---------------------------------------------------------------------------
// Static device scratch (no cudaMalloc allowed)
// ---------------------------------------------------------------------------
__device__ float g_wx_buf[(size_t)ROWS * G3];
__device__ float g_x1[(size_t)ROWS * HID];
__device__ float g_P [LAYERS * NIN * RANKSUM];
__device__ float g_Q [LAYERS * RANKSUM * G3];
__device__ float g_Pu[LAYERS * HID * RANKSUM];
__device__ float g_Qu[LAYERS * RANKSUM * G3];
__device__ float g_Ueff[LAYERS * HID * G3];

// stage-1 output as bf16 hi/lo: [row][hi 96 | lo 96]  (384 B/row)
__device__ __nv_bfloat16 g_t16[(size_t)ROWS * 192];
// Q as bf16 hi/lo: [layer][n 768][hi 96 | lo 96]
__device__ __nv_bfloat16 g_q16[(size_t)LAYERS * G3 * 192];
// P^T as bf16 hi/lo: [layer][n 96][hi 256 | lo 256]
__device__ __nv_bfloat16 g_p16[(size_t)LAYERS * 96 * 512];

// U as bf16 hi/lo in B-operand layout: per (layer, cta): [96 n][264 k-padded]
#define BPAD  264                         // 528 bytes per row (bank step 4)
#define BTILE (96 * BPAD)                 // elems per (l, c) per precision
__device__ __nv_bfloat16 g_Uhi[(size_t)LAYERS * 8 * BTILE];
__device__ __nv_bfloat16 g_Ulo[(size_t)LAYERS * 8 * BTILE];

// h exchange: A-tile images [buf 2][group 16][hi 12288B | lo 12288B]
__device__ __nv_bfloat16 g_hx[2 * 16 * 2 * 6144];

// ---------------------------------------------------------------------------
// PTX helpers (baseline-target-safe: ldmatrix + mma.sync only)
// ---------------------------------------------------------------------------
__device__ __forceinline__ uint32_t smem_u32(const void* p)
{
    uint32_t a;
    asm("{ .reg .u64 t; cvta.to.shared.u64 t, %1; cvt.u32.u64 %0, t; }"
        : "=r"(a) : "l"(p));
    return a;
}

#define LDSM4(R, addr) \
    asm volatile("ldmatrix.sync.aligned.m8n8.x4.shared.b16 {%0,%1,%2,%3}, [%4];" \
        : "=r"((R)[0]), "=r"((R)[1]), "=r"((R)[2]), "=r"((R)[3]) : "r"(addr))
#define MMA16816(D, A, B) \
    asm volatile("mma.sync.aligned.m16n8k16.row.col.f32.bf16.bf16.f32 " \
        "{%0,%1,%2,%3}, {%4,%5,%6,%7}, {%8,%9}, {%0,%1,%2,%3};" \
        : "+f"((D)[0]), "+f"((D)[1]), "+f"((D)[2]), "+f"((D)[3]) \
        : "r"((A)[0]), "r"((A)[1]), "r"((A)[2]), "r"((A)[3]), \
          "r"((B)[0]), "r"((B)[1]))

// ---------------------------------------------------------------------------
// Pack kernel: concatenate low-rank factors
// ---------------------------------------------------------------------------
__global__ void pack_kernel(const float* __restrict__ Wd, const float* __restrict__ Wdg,
                            const float* __restrict__ Wo, const float* __restrict__ Wog,
                            const float* __restrict__ Ud, const float* __restrict__ Udg,
                            const float* __restrict__ Uo, const float* __restrict__ Uog)
{
    int idx = blockIdx.x * 256 + threadIdx.x;
    const int QN = LAYERS * RANKSUM * G3;
    const int PN = LAYERS * NIN * RANKSUM;
    if (idx < QN) {
        int l = idx / (RANKSUM * G3);
        int rem = idx - l * (RANKSUM * G3);
        int r = rem / G3, n = rem - r * G3;
        g_Q[idx]  = (r < 64) ? Wdg[(l*64 + r) * G3 + n] : Wog[(l*32 + (r-64)) * G3 + n];
        g_Qu[idx] = (r < 64) ? Udg[(l*64 + r) * G3 + n] : Uog[(l*32 + (r-64)) * G3 + n];
    }
    if (idx < PN) {
        int l = idx / (NIN * RANKSUM);
        int rem = idx - l * (NIN * RANKSUM);
        int k = rem / RANKSUM, j = rem - k * RANKSUM;
        g_P[idx]  = (j < 64) ? Wd[(l*NIN + k) * 64 + j] : Wo[(l*NIN + k) * 32 + (j-64)];
        g_Pu[idx] = (j < 64) ? Ud[(l*NIN + k) * 64 + j] : Uo[(l*NIN + k) * 32 + (j-64)];
    }
}

// ---------------------------------------------------------------------------
// Split Ueff (rnn B layout), Q (wx2 B layout), P^T (s1 B layout) into hi/lo.
// ---------------------------------------------------------------------------
__global__ void split_uq()
{
    int idx = blockIdx.x * 256 + threadIdx.x;
    const int UN = LAYERS * 8 * 96 * 256;      // 393216
    const int QN = LAYERS * G3 * 96;           // 147456
    const int PN = LAYERS * 96 * 256;          // 49152
    if (idx < UN) {
        int k = idx & 255;
        int n = (idx >> 8) % 96;
        int c = (idx >> 8) / 96 % 8;
        int l = idx / (8 * 96 * 256);
        int gatecol = ((n >> 5) << 8) + (c << 5) + (n & 31);
        float v = g_Ueff[(size_t)l * HID * G3 + (size_t)k * G3 + gatecol];
        __nv_bfloat16 hi = __float2bfloat16(v);
        __nv_bfloat16 lo = __float2bfloat16(v - __bfloat162float(hi));
        size_t o = ((size_t)l * 8 + c) * BTILE + n * BPAD + k;
        g_Uhi[o] = hi;
        g_Ulo[o] = lo;
    }
    if (idx < QN) {
        int k = idx % 96;
        int n = (idx / 96) % G3;
        int l = idx / (96 * G3);
        float v = g_Q[((size_t)l * RANKSUM + k) * G3 + n];
        __nv_bfloat16 hi = __float2bfloat16(v);
        __nv_bfloat16 lo = __float2bfloat16(v - __bfloat162float(hi));
        size_t o = ((size_t)l * G3 + n) * 192 + k;
        g_q16[o]      = hi;
        g_q16[o + 96] = lo;
    }
    if (idx < PN) {
        int k = idx & 255;
        int n = (idx >> 8) % 96;
        int l = idx / (96 * 256);
        float v = g_P[(size_t)l * NIN * RANKSUM + (size_t)k * RANKSUM + n];
        __nv_bfloat16 hi = __float2bfloat16(v);
        __nv_bfloat16 lo = __float2bfloat16(v - __bfloat162float(hi));
        size_t o = ((size_t)l * 96 + n) * 512 + k;
        g_p16[o]       = hi;
        g_p16[o + 256] = lo;
    }
}

// ---------------------------------------------------------------------------
// Ueff GEMM, both layers in one launch (blockIdx.z = layer):
// Ueff[l] = Pu[l] @ Qu[l]   (256 x 768, K = 96)
// ---------------------------------------------------------------------------
__global__ void __launch_bounds__(256)
gemm_ueff(const float* __restrict__ Pu, const float* __restrict__ Qu,
          float* __restrict__ Ueff)
{
    __shared__ float As[16][64];
    __shared__ float Bs[16][68];

    const int l = blockIdx.z;
    const float* A = Pu + (size_t)l * HID * RANKSUM;
    const float* B = Qu + (size_t)l * RANKSUM * G3;
    float* C = Ueff + (size_t)l * HID * G3;

    const int tid = threadIdx.x;
    const int tm = tid >> 4, tn = tid & 15;
    const size_t bm = (size_t)blockIdx.x * 64;
    const int bn = blockIdx.y * 64;

    const int ar = tid >> 2, ak = (tid & 3) << 2;
    const int brow = tid >> 4, bcol = (tid & 15) << 2;

    float acc[4][4];
#pragma unroll
    for (int i = 0; i < 4; ++i)
#pragma unroll
        for (int j = 0; j < 4; ++j) acc[i][j] = 0.f;

    for (int k0 = 0; k0 < RANKSUM; k0 += 16) {
        float4 av = *(const float4*)(A + (bm + ar) * RANKSUM + k0 + ak);
        As[ak + 0][ar] = av.x; As[ak + 1][ar] = av.y;
        As[ak + 2][ar] = av.z; As[ak + 3][ar] = av.w;

        float4 bv = *(const float4*)(B + (size_t)(k0 + brow) * G3 + bn + bcol);
        *(float4*)&Bs[brow][bcol] = bv;
        __syncthreads();

#pragma unroll
        for (int k = 0; k < 16; ++k) {
            float4 a = *(const float4*)&As[k][tm << 2];
            float4 b = *(const float4*)&Bs[k][tn << 2];
            acc[0][0] = fmaf(a.x, b.x, acc[0][0]); acc[0][1] = fmaf(a.x, b.y, acc[0][1]);
            acc[0][2] = fmaf(a.x, b.z, acc[0][2]); acc[0][3] = fmaf(a.x, b.w, acc[0][3]);
            acc[1][0] = fmaf(a.y, b.x, acc[1][0]); acc[1][1] = fmaf(a.y, b.y, acc[1][1]);
            acc[1][2] = fmaf(a.y, b.z, acc[1][2]); acc[1][3] = fmaf(a.y, b.w, acc[1][3]);
            acc[2][0] = fmaf(a.z, b.x, acc[2][0]); acc[2][1] = fmaf(a.z, b.y, acc[2][1]);
            acc[2][2] = fmaf(a.z, b.z, acc[2][2]); acc[2][3] = fmaf(a.z, b.w, acc[2][3]);
            acc[3][0] = fmaf(a.w, b.x, acc[3][0]); acc[3][1] = fmaf(a.w, b.y, acc[3][1]);
            acc[3][2] = fmaf(a.w, b.z, acc[3][2]); acc[3][3] = fmaf(a.w, b.w, acc[3][3]);
        }
        __syncthreads();
    }

#pragma unroll
    for (int i = 0; i < 4; ++i) {
        size_t row = bm + (tm << 2) + i;
#pragma unroll
        for (int j = 0; j < 4; ++j)
            C[row * G3 + bn + (tn << 2) + j] = acc[i][j];
    }
}

// ---------------------------------------------------------------------------
// Stage-1 HMMA GEMM: T16[M,96] = x[M,256] @ P16^T
// CTA = 128 rows x 96 n. 256 threads = 8 warps (wm 0..3 x wn 0..1),
// warp tile 32m x 48n. K consumed in 4 chunks of 64; x converted to bf16
// hi/lo in-kernel while staging to smem (x read once from DRAM).
// Smem rows: [hi 64k (128B) | lo 64k (128B) | pad 16B] = 272B stride.
// ---------------------------------------------------------------------------
#define S1_A_BYTES (128 * 272)            // 34816
#define S1_B_BYTES (96 * 272)             // 26112
#define S1_SMEM    (S1_A_BYTES + S1_B_BYTES)

__global__ void __launch_bounds__(256)
gemm_s1_hmma(const float* __restrict__ x,
             const __nv_bfloat16* __restrict__ P16,   // layer base
             __nv_bfloat16* __restrict__ T16)
{
    extern __shared__ char sm[];
    char* sA = sm;
    char* sB = sm + S1_A_BYTES;

    const int tid = threadIdx.x;
    const int w = tid >> 5, lane = tid & 31;
    const int wm = w >> 1, wn = w & 1;
    const size_t bm = (size_t)blockIdx.x * 128;

    const uint32_t sAu = smem_u32(sA);
    const uint32_t sBu = smem_u32(sB);

    const int rr = lane & 7;
    // A ldmatrix (m16k16, per precision): rows wm*32 + sub, 16B col select
    const uint32_t aoff = (uint32_t)((wm * 32 + ((lane >> 3) & 1) * 8 + rr) * 272
                                     + (lane >> 4) * 16);
    // B fused hi/lo ldmatrix: q0,q1 -> hi k0/k8 ; q2,q3 -> lo k0/k8
    const int q = lane >> 3;
    const uint32_t boff = (uint32_t)(rr * 272 + ((q >> 1) * 128) + (q & 1) * 16);

    float acc[2][6][4];
#pragma unroll
    for (int mt = 0; mt < 2; ++mt)
#pragma unroll
        for (int nt = 0; nt < 6; ++nt)
#pragma unroll
            for (int i = 0; i < 4; ++i) acc[mt][nt][i] = 0.f;

    // conversion ownership: thread -> (row = tid>>1, half = tid&1)
    const int crow = tid >> 1, chalf = tid & 1;

    for (int kc = 0; kc < 4; ++kc) {
        // ---- stage A chunk: x[bm..bm+128][kc*64..+64] fp32 -> bf16 hi/lo ----
        {
            const float4* src = (const float4*)(x + (bm + crow) * NIN
                                                + kc * 64 + chalf * 32);
            char* dst = sA + crow * 272 + chalf * 64;
#pragma unroll
            for (int i = 0; i < 8; ++i) {
                float4 v = src[i];
                __nv_bfloat16 h0 = __float2bfloat16(v.x);
                __nv_bfloat16 h1 = __float2bfloat16(v.y);
                __nv_bfloat16 h2 = __float2bfloat16(v.z);
                __nv_bfloat16 h3 = __float2bfloat16(v.w);
                __nv_bfloat16 l0 = __float2bfloat16(v.x - __bfloat162float(h0));
                __nv_bfloat16 l1 = __float2bfloat16(v.y - __bfloat162float(h1));
                __nv_bfloat16 l2 = __float2bfloat16(v.z - __bfloat162float(h2));
                __nv_bfloat16 l3 = __float2bfloat16(v.w - __bfloat162float(h3));
                uint32_t hw0 = (uint32_t)__bfloat16_as_ushort(h0) |
                               ((uint32_t)__bfloat16_as_ushort(h1) << 16);
                uint32_t hw1 = (uint32_t)__bfloat16_as_ushort(h2) |
                               ((uint32_t)__bfloat16_as_ushort(h3) << 16);
                uint32_t lw0 = (uint32_t)__bfloat16_as_ushort(l0) |
                               ((uint32_t)__bfloat16_as_ushort(l1) << 16);
                uint32_t lw1 = (uint32_t)__bfloat16_as_ushort(l2) |
                               ((uint32_t)__bfloat16_as_ushort(l3) << 16);
                *(uint32_t*)(dst + i * 8)           = hw0;
                *(uint32_t*)(dst + i * 8 + 4)       = hw1;
                *(uint32_t*)(dst + 128 + i * 8)     = lw0;
                *(uint32_t*)(dst + 128 + i * 8 + 4) = lw1;
            }
        }
        // ---- stage B chunk: P16[n][kc*64..+64] hi/lo -> smem ----
        {
            // 96 n x 2 parts x 8 uint4 = 1536 units / 256 threads = 6 each
#pragma unroll
            for (int it = 0; it < 6; ++it) {
                int u = tid + 256 * it;
                int n = u >> 4;
                int part = (u >> 3) & 1;
                int i = u & 7;
                const uint4* src = (const uint4*)(P16 + (size_t)n * 512
                                                  + part * 256 + kc * 64) + i;
                *(uint4*)(sB + n * 272 + part * 128 + i * 16) = *src;
            }
        }
        __syncthreads();

        // ---- MMA over 4 ktiles of this chunk ----
#pragma unroll
        for (int kt = 0; kt < 4; ++kt) {
            uint32_t ahi[2][4], alo[2][4];
#pragma unroll
            for (int mt = 0; mt < 2; ++mt) {
                const uint32_t ab = sAu + aoff + (uint32_t)(mt * 16 * 272 + kt * 32);
                LDSM4(ahi[mt], ab);
                LDSM4(alo[mt], ab + 128);
            }
#pragma unroll
            for (int nt = 0; nt < 6; ++nt) {
                uint32_t bf[4];
                LDSM4(bf, sBu + boff + (uint32_t)((wn * 48 + nt * 8) * 272 + kt * 32));
#pragma unroll
                for (int mt = 0; mt < 2; ++mt) {
                    MMA16816(acc[mt][nt], ahi[mt], bf);      // hi*hi
                    MMA16816(acc[mt][nt], alo[mt], bf);      // lo*hi
                    MMA16816(acc[mt][nt], ahi[mt], bf + 2);  // hi*lo
                }
            }
        }
        __syncthreads();
    }

    // ---- epilogue: hi/lo bf16 split into T16 ----
    const int er = lane >> 2;
    const int ec = (lane & 3) << 1;
#pragma unroll
    for (int nt = 0; nt < 6; ++nt) {
        const int col = wn * 48 + nt * 8 + ec;
#pragma unroll
        for (int mt = 0; mt < 2; ++mt) {
#pragma unroll
            for (int rh = 0; rh < 2; ++rh) {
                const size_t row = bm + wm * 32 + mt * 16 + er + rh * 8;
                const float v0 = acc[mt][nt][rh * 2];
                const float v1 = acc[mt][nt][rh * 2 + 1];
                __nv_bfloat16 h0 = __float2bfloat16(v0);
                __nv_bfloat16 h1 = __float2bfloat16(v1);
                __nv_bfloat16 l0 = __float2bfloat16(v0 - __bfloat162float(h0));
                __nv_bfloat16 l1 = __float2bfloat16(v1 - __bfloat162float(h1));
                *(uint32_t*)(T16 + row * 192 + col) =
                    (uint32_t)__bfloat16_as_ushort(h0) |
                    ((uint32_t)__bfloat16_as_ushort(h1) << 16);
                *(uint32_t*)(T16 + row * 192 + 96 + col) =
                    (uint32_t)__bfloat16_as_ushort(l0) |
                    ((uint32_t)__bfloat16_as_ushort(l1) << 16);
            }
        }
    }
}

// ---------------------------------------------------------------------------
// Stage-2 HMMA GEMM: wx[M,768] = T16[M,96] @ Q16^T + bias  (unchanged R9/R10)
// ---------------------------------------------------------------------------
#define WX2_A_BYTES (128 * 416)
#define WX2_B_BYTES (64 * 416)
#define WX2_SMEM    (WX2_A_BYTES + WX2_B_BYTES)

__global__ void __launch_bounds__(256)
wx2_hmma(const __nv_bfloat16* __restrict__ T16,
         const __nv_bfloat16* __restrict__ Q16,
         const float* __restrict__ bias,
         float* __restrict__ C)
{
    extern __shared__ char sm[];
    char* sA = sm;
    char* sB = sm + WX2_A_BYTES;

    const int tid = threadIdx.x;
    const int w = tid >> 5, lane = tid & 31;
    const int wm = w >> 1, wn = w & 1;
    const size_t bm = (size_t)blockIdx.y * 128;
    const int bn = blockIdx.x * 64;

    {
        const uint4* src = (const uint4*)T16 + bm * 24;
#pragma unroll
        for (int i = 0; i < 12; ++i) {
            int u = tid + 256 * i;
            int row = u / 24, ir = u - row * 24;
            uint32_t off = (uint32_t)(row * 416 + ir * 16 + ((ir >= 12) ? 16 : 0));
            *(uint4*)(sA + off) = src[u];
        }
        const uint4* srcB = (const uint4*)Q16 + (size_t)bn * 24;
#pragma unroll
        for (int i = 0; i < 6; ++i) {
            int u = tid + 256 * i;
            int row = u / 24, ir = u - row * 24;
            uint32_t off = (uint32_t)(row * 416 + ir * 16 + ((ir >= 12) ? 16 : 0));
            *(uint4*)(sB + off) = srcB[u];
        }
    }
    __syncthreads();

    const uint32_t sAu = smem_u32(sA);
    const uint32_t sBu = smem_u32(sB);

    const int rr = lane & 7;
    const uint32_t aoff = (uint32_t)((wm * 32 + ((lane >> 3) & 1) * 8 + rr) * 416
                                     + (lane >> 4) * 16);
    const int q = lane >> 3;
    const uint32_t boff = (uint32_t)((wn * 32 + rr) * 416 + (q & 1) * 16
                                     + (q >> 1) * 208);

    float acc[2][4][4];
#pragma unroll
    for (int mt = 0; mt < 2; ++mt)
#pragma unroll
        for (int nt = 0; nt < 4; ++nt)
#pragma unroll
            for (int i = 0; i < 4; ++i) acc[mt][nt][i] = 0.f;

#pragma unroll
    for (int kt = 0; kt < 6; ++kt) {
        uint32_t ahi[2][4], alo[2][4];
#pragma unroll
        for (int mt = 0; mt < 2; ++mt) {
            const uint32_t ab = sAu + aoff + (uint32_t)(mt * 16 * 416 + kt * 32);
            LDSM4(ahi[mt], ab);
            LDSM4(alo[mt], ab + 208);
        }
#pragma unroll
        for (int nt = 0; nt < 4; ++nt) {
            uint32_t bf[4];
            LDSM4(bf, sBu + boff + (uint32_t)(nt * 8 * 416 + kt * 32));
#pragma unroll
            for (int mt = 0; mt < 2; ++mt) {
                MMA16816(acc[mt][nt], ahi[mt], bf);
                MMA16816(acc[mt][nt], alo[mt], bf);
                MMA16816(acc[mt][nt], ahi[mt], bf + 2);
            }
        }
    }

    const int er = lane >> 2;
    const int ec = (lane & 3) << 1;
#pragma unroll
    for (int nt = 0; nt < 4; ++nt) {
        const int col = bn + wn * 32 + nt * 8 + ec;
        const float b0 = bias[col], b1 = bias[col + 1];
#pragma unroll
        for (int mt = 0; mt < 2; ++mt) {
            const size_t r0 = bm + wm * 32 + mt * 16 + er;
            *(float2*)(C + r0 * G3 + col) =
                make_float2(acc[mt][nt][0] + b0, acc[mt][nt][1] + b1);
            *(float2*)(C + (r0 + 8) * G3 + col) =
                make_float2(acc[mt][nt][2] + b0, acc[mt][nt][3] + b1);
        }
    }
}

__device__ __forceinline__ float sigmoidf_(float x)
{
    return __fdividef(1.f, 1.f + __expf(-x));
}
__device__ __forceinline__ float tanhf_(float x)
{
    return __fdividef(2.f, 1.f + __expf(-2.f * x)) - 1.f;
}

// ---------------------------------------------------------------------------
// HMMA recurrent kernel (identical to R10 winner: B fragments hoisted).
// ---------------------------------------------------------------------------
#define A_BYTES  24576
#define B_BYTES  (BTILE * 2)
#define RED_BYTES (3 * 4 * 32 * 12 * 4)
#define RNN_SMEM (A_BYTES + 2 * B_BYTES + RED_BYTES)

__global__ void __cluster_dims__(8, 1, 1) __launch_bounds__(512, 1)
rnn_hmma(const __nv_bfloat16* __restrict__ Uhi8,
         const __nv_bfloat16* __restrict__ Ulo8,
         const float* __restrict__ wx,
         float* __restrict__ out_x,
         float* __restrict__ hT_out,
         __nv_bfloat16* __restrict__ hx)
{
    extern __shared__ char sm[];
    char* sA  = sm;
    char* sBh = sm + A_BYTES;
    char* sBl = sBh + B_BYTES;
    float* red = (float*)(sBl + B_BYTES);

    const int c  = blockIdx.x & 7;
    const int g  = blockIdx.x >> 3;
    const int tid = threadIdx.x;
    const int w = tid >> 5, lane = tid & 31;
    const int kq = w >> 2;
    const int cg = w & 3;

    {
        const uint4* s0 = (const uint4*)(Uhi8 + (size_t)c * BTILE);
        const uint4* s1 = (const uint4*)(Ulo8 + (size_t)c * BTILE);
        uint4* d0 = (uint4*)sBh;
        uint4* d1 = (uint4*)sBl;
        for (int i = tid; i < B_BYTES / 16; i += 512) { d0[i] = s0[i]; d1[i] = s1[i]; }
        uint4 z4 = make_uint4(0u, 0u, 0u, 0u);
        uint4* a4 = (uint4*)sA;
        for (int i = tid; i < A_BYTES / 16; i += 512) a4[i] = z4;
    }
    __syncthreads();

    const uint32_t sAu  = smem_u32(sA);
    const uint32_t sBhu = smem_u32(sBh);
    const uint32_t sBlu = smem_u32(sBl);
    const int q = lane >> 3, rr = lane & 7;
    const uint32_t aoff = (uint32_t)(((q & 1) * 8 + rr) * 48 + (q >> 1) * 16);
    const uint32_t bbase = ((q < 2) ? sBhu : sBlu)
                         + (uint32_t)(rr * 528 + (q & 1) * 16)
                         + (uint32_t)((cg << 3) * 528);
    const uint32_t bz = 0, br = 32 * 528, bc = 64 * 528;

    uint32_t bZ[4][4], bR[4][4], bC[4][4];
#pragma unroll
    for (int i = 0; i < 4; ++i) {
        const uint32_t ko = bbase + (uint32_t)(((kq << 2) + i) * 32);
        LDSM4(bZ[i], ko + bz);
        LDSM4(bR[i], ko + br);
        LDSM4(bC[i], ko + bc);
    }

    const int r1 = lane >> 2;
    const int coll = (cg << 3) + ((lane & 3) << 1);
    const int hidg = (c << 5) + coll;
    const size_t brow1 = (size_t)(g * 16 + r1);
    const size_t brow2 = brow1 + 8;
    const int kt = hidg >> 4, kin = hidg & 15;
    const uint32_t po1 = (uint32_t)(kt * 768 + r1 * 48 + kin * 2);
    const uint32_t po2 = po1 + 8 * 48;

    float hp[4] = {0.f, 0.f, 0.f, 0.f};

    float2 wxv[3][2];
    if (kq == 0) {
        const float* p1 = wx + (brow1 * SEQ) * G3 + hidg;
        const float* p2 = wx + (brow2 * SEQ) * G3 + hidg;
        wxv[0][0] = *(const float2*)(p1);       wxv[0][1] = *(const float2*)(p2);
        wxv[1][0] = *(const float2*)(p1 + 256); wxv[1][1] = *(const float2*)(p2 + 256);
        wxv[2][0] = *(const float2*)(p1 + 512); wxv[2][1] = *(const float2*)(p2 + 512);
    }

    for (int t = 0; t < SEQ; ++t) {
        float2 wxn[3][2];
        if (kq == 0) {
            const int tn = (t + 1 < SEQ) ? t + 1 : t;
            const float* p1 = wx + (brow1 * SEQ + tn) * G3 + hidg;
            const float* p2 = wx + (brow2 * SEQ + tn) * G3 + hidg;
            wxn[0][0] = *(const float2*)(p1);       wxn[0][1] = *(const float2*)(p2);
            wxn[1][0] = *(const float2*)(p1 + 256); wxn[1][1] = *(const float2*)(p2 + 256);
            wxn[2][0] = *(const float2*)(p1 + 512); wxn[2][1] = *(const float2*)(p2 + 512);
        }

        float dz[4] = {0.f, 0.f, 0.f, 0.f};
        float dr[4] = {0.f, 0.f, 0.f, 0.f};
        float dc[4] = {0.f, 0.f, 0.f, 0.f};
#pragma unroll
        for (int i = 0; i < 4; ++i) {
            const int ktl = (kq << 2) + i;
            uint32_t ah[4], al[4];
            const uint32_t ab = sAu + (uint32_t)(ktl * 768) + aoff;
            LDSM4(ah, ab);
            LDSM4(al, ab + 12288);

            MMA16816(dz, ah, bZ[i]);
            MMA16816(dz, al, bZ[i]);
            MMA16816(dz, ah, bZ[i] + 2);

            MMA16816(dr, ah, bR[i]);
            MMA16816(dr, al, bR[i]);
            MMA16816(dr, ah, bR[i] + 2);

            MMA16816(dc, ah, bC[i]);
            MMA16816(dc, al, bC[i]);
            MMA16816(dc, ah, bC[i] + 2);
        }

        if (kq) {
            float* s = red + (((kq - 1) * 4 + cg) * 32 + lane) * 12;
            *(float4*)(s + 0) = make_float4(dz[0], dz[1], dz[2], dz[3]);
            *(float4*)(s + 4) = make_float4(dr[0], dr[1], dr[2], dr[3]);
            *(float4*)(s + 8) = make_float4(dc[0], dc[1], dc[2], dc[3]);
        }
        __syncthreads();

        float hn[4];
        if (kq == 0) {
#pragma unroll
            for (int s3 = 0; s3 < 3; ++s3) {
                const float* s = red + ((s3 * 4 + cg) * 32 + lane) * 12;
                const float4 vz = *(const float4*)(s + 0);
                const float4 vr = *(const float4*)(s + 4);
                const float4 vc = *(const float4*)(s + 8);
                dz[0] += vz.x; dz[1] += vz.y; dz[2] += vz.z; dz[3] += vz.w;
                dr[0] += vr.x; dr[1] += vr.y; dr[2] += vr.z; dr[3] += vr.w;
                dc[0] += vc.x; dc[1] += vc.y; dc[2] += vc.z; dc[3] += vc.w;
            }

#pragma unroll
            for (int i = 0; i < 4; ++i) {
                const int rs = i >> 1;
                const float wzv = (i & 1) ? wxv[0][rs].y : wxv[0][rs].x;
                const float wrv = (i & 1) ? wxv[1][rs].y : wxv[1][rs].x;
                const float wcv = (i & 1) ? wxv[2][rs].y : wxv[2][rs].x;
                const float z  = sigmoidf_(wzv + dz[i]);
                const float rg = sigmoidf_(wrv + dr[i]);
                const float cc = tanhf_(wcv + rg * dc[i]);
                hn[i] = z * hp[i] + (1.f - z) * cc;
                hp[i] = hn[i];
            }

            const int nb = (t + 1) & 1;
            char* ex = (char*)hx + (size_t)(nb * 16 + g) * A_BYTES;
            uint32_t hw[2], lw[2];
#pragma unroll
            for (int s2 = 0; s2 < 2; ++s2) {
                __nv_bfloat16 h0 = __float2bfloat16(hn[2*s2]);
                __nv_bfloat16 h1 = __float2bfloat16(hn[2*s2+1]);
                __nv_bfloat16 l0 = __float2bfloat16(hn[2*s2]   - __bfloat162float(h0));
                __nv_bfloat16 l1 = __float2bfloat16(hn[2*s2+1] - __bfloat162float(h1));
                hw[s2] = (uint32_t)__bfloat16_as_ushort(h0) |
                         ((uint32_t)__bfloat16_as_ushort(h1) << 16);
                lw[s2] = (uint32_t)__bfloat16_as_ushort(l0) |
                         ((uint32_t)__bfloat16_as_ushort(l1) << 16);
            }
            *(uint32_t*)(ex + po1)         = hw[0];
            *(uint32_t*)(ex + po2)         = hw[1];
            *(uint32_t*)(ex + 12288 + po1) = lw[0];
            *(uint32_t*)(ex + 12288 + po2) = lw[1];
        }

        asm volatile("barrier.cluster.arrive.aligned;" ::: "memory");

        if (kq == 0) {
            float* o1 = out_x + (brow1 * SEQ + t) * HID + hidg;
            float* o2 = out_x + (brow2 * SEQ + t) * HID + hidg;
            *(float2*)o1 = make_float2(hn[0], hn[1]);
            *(float2*)o2 = make_float2(hn[2], hn[3]);
            if (t == SEQ - 1) {
                *(float2*)(hT_out + brow1 * 512 + hidg) = make_float2(hn[0], hn[1]);
                *(float2*)(hT_out + brow2 * 512 + hidg) = make_float2(hn[2], hn[3]);
            }
#pragma unroll
            for (int a3 = 0; a3 < 3; ++a3) {
                wxv[a3][0] = wxn[a3][0];
                wxv[a3][1] = wxn[a3][1];
            }
        }

        asm volatile("barrier.cluster.wait.aligned;" ::: "memory");

        {
            const int nb = (t + 1) & 1;
            const uint4* src = (const uint4*)((const char*)hx +
                                              (size_t)(nb * 16 + g) * A_BYTES);
            uint4* dst = (uint4*)sA;
#pragma unroll
            for (int i = 0; i < 3; ++i)
                dst[tid + 512 * i] = src[tid + 512 * i];
        }
        __syncthreads();
    }
}

// ---------------------------------------------------------------------------
// Launch
// ---------------------------------------------------------------------------
extern "C" void kernel_launch(void* const* d_in, const int* in_sizes, int n_in,
                              void* d_out, int out_size)
{
    const float* x   = (const float*)d_in[0];
    const float* Wd  = (const float*)d_in[1];
    const float* Wdg = (const float*)d_in[2];
    const float* Wo  = (const float*)d_in[3];
    const float* Wog = (const float*)d_in[4];
    const float* Ud  = (const float*)d_in[5];
    const float* Udg = (const float*)d_in[6];
    const float* Uo  = (const float*)d_in[7];
    const float* Uog = (const float*)d_in[8];
    const float* bb  = (const float*)d_in[9];
    float* out = (float*)d_out;

    float *pWX, *pX1, *pP, *pQ, *pPu, *pQu, *pUeff;
    __nv_bfloat16 *pUhi, *pUlo, *pHX, *pT16, *pQ16, *pP16;
    cudaGetSymbolAddress((void**)&pWX,   g_wx_buf);
    cudaGetSymbolAddress((void**)&pX1,   g_x1);
    cudaGetSymbolAddress((void**)&pP,    g_P);
    cudaGetSymbolAddress((void**)&pQ,    g_Q);
    cudaGetSymbolAddress((void**)&pPu,   g_Pu);
    cudaGetSymbolAddress((void**)&pQu,   g_Qu);
    cudaGetSymbolAddress((void**)&pUeff, g_Ueff);
    cudaGetSymbolAddress((void**)&pUhi,  g_Uhi);
    cudaGetSymbolAddress((void**)&pUlo,  g_Ulo);
    cudaGetSymbolAddress((void**)&pHX,   g_hx);
    cudaGetSymbolAddress((void**)&pT16,  g_t16);
    cudaGetSymbolAddress((void**)&pQ16,  g_q16);
    cudaGetSymbolAddress((void**)&pP16,  g_p16);

    cudaFuncSetAttribute(rnn_hmma, cudaFuncAttributeMaxDynamicSharedMemorySize,
                         RNN_SMEM);
    cudaFuncSetAttribute(wx2_hmma, cudaFuncAttributeMaxDynamicSharedMemorySize,
                         WX2_SMEM);
    cudaFuncSetAttribute(gemm_s1_hmma, cudaFuncAttributeMaxDynamicSharedMemorySize,
                         S1_SMEM);

    pack_kernel<<<(LAYERS * RANKSUM * G3 + 255) / 256, 256>>>(Wd, Wdg, Wo, Wog,
                                                              Ud, Udg, Uo, Uog);
    gemm_ueff<<<dim3(HID / 64, G3 / 64, LAYERS), 256>>>(pPu, pQu, pUeff);
    split_uq<<<(LAYERS * 8 * 96 * 256 + 255) / 256, 256>>>();

    const size_t OUT0 = (size_t)ROWS * HID;

    for (int l = 0; l < LAYERS; ++l) {
        const float* xin = (l == 0) ? x : pX1;
        gemm_s1_hmma<<<ROWS / 128, 256, S1_SMEM>>>(
            xin, pP16 + (size_t)l * 96 * 512, pT16);
        wx2_hmma<<<dim3(G3 / 64, ROWS / 128), 256, WX2_SMEM>>>(
            pT16, pQ16 + (size_t)l * G3 * 192, bb + l * G3, pWX);
        float* ox = (l == LAYERS - 1) ? out : pX1;
        rnn_hmma<<<128, 512, RNN_SMEM>>>(
            pUhi + (size_t)l * 8 * BTILE, pUlo + (size_t)l * 8 * BTILE,
            pWX, ox, out + OUT0 + l * HID, pHX);
    }
}